// round 3
// baseline (speedup 1.0000x reference)
#include <cuda_runtime.h>
#include <cstdint>

#define MAXN 250000
#define DD 128
#define HH 256

// ---------------- scratch (device globals: no allocations allowed) ----------------
__device__ float g_hidden[MAXN * DD];
__device__ float g_sp[MAXN * DD];
__device__ float g_sc[MAXN * DD];
__device__ int   g_cnt_self[MAXN];
__device__ int   g_cnt_par[MAXN];
__device__ float g_biasP[HH];
__device__ float g_biasC[HH];

// ---------------- small precompute: edge vectors -> folded layer-1 biases ----------
__global__ void precompute_kernel(const float* __restrict__ Ew1, const float* __restrict__ Eb1,
                                  const float* __restrict__ Ew2, const float* __restrict__ Eb2,
                                  const float* __restrict__ Pw1, const float* __restrict__ Pb1,
                                  const float* __restrict__ Cw1, const float* __restrict__ Cb1,
                                  float* __restrict__ biasP, float* __restrict__ biasC) {
    __shared__ float hin[HH], hout[HH], ein[DD], eout[DD];
    int t = threadIdx.x;
    if (t < HH) {
        hin[t]  = fmaxf(Ew1[t] + Eb1[t], 0.f);  // x = 1
        hout[t] = fmaxf(Eb1[t], 0.f);           // x = 0
    }
    __syncthreads();
    if (t < DD) {
        float si = Eb2[t], so = Eb2[t];
        for (int j = 0; j < HH; j++) {
            si += hin[j]  * Ew2[j * DD + t];
            so += hout[j] * Ew2[j * DD + t];
        }
        ein[t]  = fmaxf(si, 0.f);
        eout[t] = fmaxf(so, 0.f);
    }
    __syncthreads();
    if (t < HH) {
        float bp = Pb1[t], bc = Cb1[t];
        for (int d = 0; d < DD; d++) {
            bp += eout[d] * Pw1[(2 * DD + d) * HH + t];
            bc += ein[d]  * Cw1[(2 * DD + d) * HH + t];
        }
        biasP[t] = bp;
        biasC[t] = bc;
    }
}

__global__ void count_kernel(const int* __restrict__ si, const int* __restrict__ pi,
                             int* __restrict__ cs, int* __restrict__ cp, int E) {
    int e = blockIdx.x * blockDim.x + threadIdx.x;
    if (e < E) {
        atomicAdd(&cs[si[e]], 1);
        atomicAdd(&cp[pi[e]], 1);
    }
}

// ---------------- fused 2-layer MLP core ----------------
// Block: 256 threads, BM = 64 rows.
// Layer 1: T[64][256] = relu(As[64][K1] @ W1 + bias1)   (8x8 microtile, 32x8 thread grid)
// Layer 2: acc2[64][128] = As2 @ W2 + b2                (8x4 microtile)  (relu by caller)
// Weights streamed from L2 in 32-row tiles, register->smem double buffered.
// w1 passed as up to three 128-row segment base pointers (allows the self/parent
// half swap for MLP_C without reshuffling As).
template <int K1>
__device__ __forceinline__ void fused_mlp(
    const float* __restrict__ As, float* __restrict__ Ts, float* __restrict__ Ws,
    const float* __restrict__ w1s0, const float* __restrict__ w1s1, const float* __restrict__ w1s2,
    const float* __restrict__ bias1, const float* __restrict__ w2, const float* __restrict__ b2,
    float acc2[8][4]) {
    const int tid = threadIdx.x;
    const int tx = tid & 31, ty = tid >> 5;
    const int n0 = tx * 8, m0 = ty * 8;
    constexpr int T = K1 / 32;

    float acc[8][8];
#pragma unroll
    for (int j = 0; j < 8; j++) {
        float b = bias1[n0 + j];
#pragma unroll
        for (int i = 0; i < 8; i++) acc[i][j] = b;
    }

    __syncthreads();  // As visible to all; Ws free (prior phase done)
    {
        const float* src = w1s0;
#pragma unroll
        for (int i = 0; i < 8; i++) {
            int f = tid + i * 256;
            *(float4*)(Ws + f * 4) = *(const float4*)(src + f * 4);
        }
    }
    __syncthreads();
    int buf = 0;
    for (int t = 0; t < T; t++) {
        float4 pre[8];
        if (t + 1 < T) {
            int k0n = (t + 1) * 32;
            const float* src = (k0n < 128) ? (w1s0 + k0n * 256)
                             : (k0n < 256) ? (w1s1 + (k0n - 128) * 256)
                                           : (w1s2 + (k0n - 256) * 256);
#pragma unroll
            for (int i = 0; i < 8; i++) {
                int f = tid + i * 256;
                pre[i] = *(const float4*)(src + f * 4);
            }
        }
        const float* W = Ws + buf * 8192;
        const int k0 = t * 32;
#pragma unroll 4
        for (int k = 0; k < 32; k++) {
            float4 b0 = *(const float4*)(W + k * 256 + n0);
            float4 b1 = *(const float4*)(W + k * 256 + n0 + 4);
            float bb[8] = {b0.x, b0.y, b0.z, b0.w, b1.x, b1.y, b1.z, b1.w};
            float aa[8];
#pragma unroll
            for (int i = 0; i < 8; i++) aa[i] = As[(m0 + i) * K1 + k0 + k];
#pragma unroll
            for (int i = 0; i < 8; i++)
#pragma unroll
                for (int j = 0; j < 8; j++) acc[i][j] = fmaf(aa[i], bb[j], acc[i][j]);
        }
        if (t + 1 < T) {
#pragma unroll
            for (int i = 0; i < 8; i++) {
                int f = tid + i * 256;
                *(float4*)(Ws + (buf ^ 1) * 8192 + f * 4) = pre[i];
            }
            __syncthreads();
            buf ^= 1;
        }
    }
    // relu -> Ts
#pragma unroll
    for (int i = 0; i < 8; i++)
#pragma unroll
        for (int j = 0; j < 8; j++) Ts[(m0 + i) * 256 + n0 + j] = fmaxf(acc[i][j], 0.f);
    __syncthreads();  // Ts ready; all layer-1 Ws reads done

    // ---- layer 2 ----
    const int n2 = (tid & 31) * 4, m2 = (tid >> 5) * 8;
#pragma unroll
    for (int j = 0; j < 4; j++) {
        float b = b2[n2 + j];
#pragma unroll
        for (int i = 0; i < 8; i++) acc2[i][j] = b;
    }
    {
#pragma unroll
        for (int i = 0; i < 4; i++) {
            int f = tid + i * 256;
            *(float4*)(Ws + f * 4) = *(const float4*)(w2 + f * 4);
        }
    }
    __syncthreads();
    buf = 0;
    for (int t = 0; t < 8; t++) {
        float4 pre[4];
        if (t + 1 < 8) {
            const float* src = w2 + (t + 1) * 32 * 128;
#pragma unroll
            for (int i = 0; i < 4; i++) {
                int f = tid + i * 256;
                pre[i] = *(const float4*)(src + f * 4);
            }
        }
        const float* W = Ws + buf * 8192;
        const int k0 = t * 32;
#pragma unroll 4
        for (int k = 0; k < 32; k++) {
            float4 bv = *(const float4*)(W + k * 128 + n2);
            float bb[4] = {bv.x, bv.y, bv.z, bv.w};
            float aa[8];
#pragma unroll
            for (int i = 0; i < 8; i++) aa[i] = Ts[(m2 + i) * 256 + k0 + k];
#pragma unroll
            for (int i = 0; i < 8; i++)
#pragma unroll
                for (int j = 0; j < 4; j++) acc2[i][j] = fmaf(aa[i], bb[j], acc2[i][j]);
        }
        if (t + 1 < 8) {
#pragma unroll
            for (int i = 0; i < 4; i++) {
                int f = tid + i * 256;
                *(float4*)(Ws + (buf ^ 1) * 8192 + f * 4) = pre[i];
            }
            __syncthreads();
            buf ^= 1;
        }
    }
}

// ---------------- kernel: hidden = MLP_V(batch_token) ----------------
// smem: As 64*128 | Ts 64*256 | Ws 2*32*256   = 40960 floats = 160 KB
__global__ __launch_bounds__(256, 1) void mlp_v_kernel(
    const float* __restrict__ x,
    const float* __restrict__ Vw1, const float* __restrict__ Vb1,
    const float* __restrict__ Vw2, const float* __restrict__ Vb2,
    float* __restrict__ hidden, int Nn) {
    extern __shared__ float sm[];
    float* As = sm;
    float* Ts = As + 64 * 128;
    float* Ws = Ts + 64 * 256;
    const int tid = threadIdx.x, lane = tid & 31;
    const int i0 = blockIdx.x * 64;
    for (int r = tid >> 5; r < 64; r += 8) {
        int i = i0 + r;
        float4 v = make_float4(0.f, 0.f, 0.f, 0.f);
        if (i < Nn) v = *(const float4*)(x + (long)i * 128 + lane * 4);
        *(float4*)(As + r * 128 + lane * 4) = v;
    }
    float acc2[8][4];
    fused_mlp<128>(As, Ts, Ws, Vw1, Vw1, Vw1, Vb1, Vw2, Vb2, acc2);
    const int n2 = (tid & 31) * 4, m2 = (tid >> 5) * 8;
#pragma unroll
    for (int i = 0; i < 8; i++) {
        int node = i0 + m2 + i;
        if (node < Nn) {
            float4 o;
            o.x = fmaxf(acc2[i][0], 0.f);
            o.y = fmaxf(acc2[i][1], 0.f);
            o.z = fmaxf(acc2[i][2], 0.f);
            o.w = fmaxf(acc2[i][3], 0.f);
            *(float4*)(hidden + (long)node * 128 + n2) = o;
        }
    }
}

// ---------------- kernel: per-edge MLP_P and MLP_C + scatter-sum ----------------
// smem: As 64*256 | Ts 64*256 | Ws 2*32*256 | idx 2*64 ints  = 197120 B
__global__ __launch_bounds__(256, 1) void edge_kernel(
    const float* __restrict__ hidden,
    const int* __restrict__ self_idx, const int* __restrict__ parent_idx,
    const float* __restrict__ Pw1, const float* __restrict__ Pw2, const float* __restrict__ Pb2,
    const float* __restrict__ Cw1, const float* __restrict__ Cw2, const float* __restrict__ Cb2,
    const float* __restrict__ biasP, const float* __restrict__ biasC,
    float* __restrict__ sp, float* __restrict__ sc, int E) {
    extern __shared__ float sm[];
    float* As = sm;            // [64][256]: [0:128]=parent, [128:256]=self
    float* Ts = As + 64 * 256;
    float* Ws = Ts + 64 * 256;
    int* sIdx = (int*)(Ws + 16384);
    int* pIdx = sIdx + 64;
    const int tid = threadIdx.x, lane = tid & 31;
    const int e0 = blockIdx.x * 64;
    if (tid < 64) {
        int e = e0 + tid;
        sIdx[tid] = (e < E) ? self_idx[e] : -1;
        pIdx[tid] = (e < E) ? parent_idx[e] : -1;
    }
    __syncthreads();
    for (int r = tid >> 5; r < 128; r += 8) {
        int er = r & 63;
        bool isPar = r < 64;
        int idx = isPar ? pIdx[er] : sIdx[er];
        float4 v = make_float4(0.f, 0.f, 0.f, 0.f);
        if (idx >= 0) v = *(const float4*)(hidden + (long)idx * 128 + lane * 4);
        *(float4*)(As + er * 256 + (isPar ? 0 : 128) + lane * 4) = v;
    }
    float acc2[8][4];
    const int n2 = (tid & 31) * 4, m2 = (tid >> 5) * 8;

    // MLP_P: inp = [parent | self] -> Pw1 rows [0:128], [128:256]; scatter by self_idx
    fused_mlp<256>(As, Ts, Ws, Pw1, Pw1 + 128 * 256, Pw1, biasP, Pw2, Pb2, acc2);
#pragma unroll
    for (int i = 0; i < 8; i++) {
        int idx = sIdx[m2 + i];
        if (idx >= 0) {
#pragma unroll
            for (int j = 0; j < 4; j++)
                atomicAdd(sp + (long)idx * 128 + n2 + j, fmaxf(acc2[i][j], 0.f));
        }
    }
    // MLP_C: inp = [self | parent] -> swap weight halves; scatter by parent_idx
    fused_mlp<256>(As, Ts, Ws, Cw1 + 128 * 256, Cw1, Cw1, biasC, Cw2, Cb2, acc2);
#pragma unroll
    for (int i = 0; i < 8; i++) {
        int idx = pIdx[m2 + i];
        if (idx >= 0) {
#pragma unroll
            for (int j = 0; j < 4; j++)
                atomicAdd(sc + (long)idx * 128 + n2 + j, fmaxf(acc2[i][j], 0.f));
        }
    }
}

// ---------------- kernel: node aggregation (mean + masks + MLP_A + residual) ------
// smem: As 64*384 | Ts 64*256 | Ws 2*32*256  = 229376 B
__global__ __launch_bounds__(256, 1) void node_kernel(
    const float* __restrict__ hidden,
    const float* __restrict__ sp, const float* __restrict__ sc,
    const int* __restrict__ cntS, const int* __restrict__ cntP,
    const float* __restrict__ root_mask, const float* __restrict__ leaf_mask,
    const float* __restrict__ start_tok, const float* __restrict__ end_tok,
    const float* __restrict__ Aw1, const float* __restrict__ Ab1,
    const float* __restrict__ Aw2, const float* __restrict__ Ab2,
    float* __restrict__ out, int Nn) {
    extern __shared__ float sm[];
    float* As = sm;            // [64][384]: hidden | S_p | S_c
    float* Ts = As + 64 * 384;
    float* Ws = Ts + 64 * 256;
    const int tid = threadIdx.x, lane = tid & 31;
    const int i0 = blockIdx.x * 64;
    float4 st = *(const float4*)(start_tok + lane * 4);
    float4 et = *(const float4*)(end_tok + lane * 4);
    for (int r = tid >> 5; r < 64; r += 8) {
        int i = i0 + r;
        float4 h = make_float4(0.f, 0.f, 0.f, 0.f), spv = h, scv = h;
        if (i < Nn) {
            h = *(const float4*)(hidden + (long)i * 128 + lane * 4);
            int csv = cntS[i]; if (csv < 1) csv = 1;
            int cpv = cntP[i]; if (cpv < 1) cpv = 1;
            float invS = 1.0f / (float)csv;
            float invP = 1.0f / (float)cpv;
            float rm = root_mask[i], lm = leaf_mask[i];
            spv = *(const float4*)(sp + (long)i * 128 + lane * 4);
            scv = *(const float4*)(sc + (long)i * 128 + lane * 4);
            spv.x = spv.x * invS + rm * st.x; spv.y = spv.y * invS + rm * st.y;
            spv.z = spv.z * invS + rm * st.z; spv.w = spv.w * invS + rm * st.w;
            scv.x = scv.x * invP + lm * et.x; scv.y = scv.y * invP + lm * et.y;
            scv.z = scv.z * invP + lm * et.z; scv.w = scv.w * invP + lm * et.w;
        }
        *(float4*)(As + r * 384 + lane * 4) = h;
        *(float4*)(As + r * 384 + 128 + lane * 4) = spv;
        *(float4*)(As + r * 384 + 256 + lane * 4) = scv;
    }
    float acc2[8][4];
    fused_mlp<384>(As, Ts, Ws, Aw1, Aw1 + 128 * 256, Aw1 + 256 * 256, Ab1, Aw2, Ab2, acc2);
    const int n2 = (tid & 31) * 4, m2 = (tid >> 5) * 8;
#pragma unroll
    for (int i = 0; i < 8; i++) {
        int node = i0 + m2 + i;
        if (node < Nn) {
            int r = m2 + i;
            float4 o;
            o.x = As[r * 384 + n2 + 0] + fmaxf(acc2[i][0], 0.f);
            o.y = As[r * 384 + n2 + 1] + fmaxf(acc2[i][1], 0.f);
            o.z = As[r * 384 + n2 + 2] + fmaxf(acc2[i][2], 0.f);
            o.w = As[r * 384 + n2 + 3] + fmaxf(acc2[i][3], 0.f);
            *(float4*)(out + (long)node * 128 + n2) = o;
        }
    }
}

// ---------------- host launch ----------------
extern "C" void kernel_launch(void* const* d_in, const int* in_sizes, int n_in,
                              void* d_out, int out_size) {
    const float* batch_token = (const float*)d_in[0];
    const int*   self_idx    = (const int*)d_in[1];
    const int*   parent_idx  = (const int*)d_in[2];
    const float* root_mask   = (const float*)d_in[3];
    const float* leaf_mask   = (const float*)d_in[4];
    const float* start_tok   = (const float*)d_in[5];
    const float* end_tok     = (const float*)d_in[6];
    const float* Vw1 = (const float*)d_in[7];
    const float* Vb1 = (const float*)d_in[8];
    const float* Vw2 = (const float*)d_in[9];
    const float* Vb2 = (const float*)d_in[10];
    const float* Ew1 = (const float*)d_in[11];
    const float* Eb1 = (const float*)d_in[12];
    const float* Ew2 = (const float*)d_in[13];
    const float* Eb2 = (const float*)d_in[14];
    const float* Pw1 = (const float*)d_in[15];
    const float* Pb1 = (const float*)d_in[16];
    const float* Pw2 = (const float*)d_in[17];
    const float* Pb2 = (const float*)d_in[18];
    const float* Cw1 = (const float*)d_in[19];
    const float* Cb1 = (const float*)d_in[20];
    const float* Cw2 = (const float*)d_in[21];
    const float* Cb2 = (const float*)d_in[22];
    const float* Aw1 = (const float*)d_in[23];
    const float* Ab1 = (const float*)d_in[24];
    const float* Aw2 = (const float*)d_in[25];
    const float* Ab2 = (const float*)d_in[26];

    const int Nn = in_sizes[0] / 128;
    const int E  = in_sizes[1];

    float *hid, *sp, *sc, *bP, *bC;
    int *cs, *cp;
    cudaGetSymbolAddress((void**)&hid, g_hidden);
    cudaGetSymbolAddress((void**)&sp,  g_sp);
    cudaGetSymbolAddress((void**)&sc,  g_sc);
    cudaGetSymbolAddress((void**)&cs,  g_cnt_self);
    cudaGetSymbolAddress((void**)&cp,  g_cnt_par);
    cudaGetSymbolAddress((void**)&bP,  g_biasP);
    cudaGetSymbolAddress((void**)&bC,  g_biasC);

    const int SMEM_V = (64 * 128 + 64 * 256 + 2 * 32 * 256) * 4;              // 163840
    const int SMEM_E = (64 * 256 + 64 * 256 + 2 * 32 * 256) * 4 + 2 * 64 * 4; // 197120
    const int SMEM_N = (64 * 384 + 64 * 256 + 2 * 32 * 256) * 4;              // 229376
    cudaFuncSetAttribute(mlp_v_kernel, cudaFuncAttributeMaxDynamicSharedMemorySize, SMEM_V);
    cudaFuncSetAttribute(edge_kernel,  cudaFuncAttributeMaxDynamicSharedMemorySize, SMEM_E);
    cudaFuncSetAttribute(node_kernel,  cudaFuncAttributeMaxDynamicSharedMemorySize, SMEM_N);

    precompute_kernel<<<1, 256>>>(Ew1, Eb1, Ew2, Eb2, Pw1, Pb1, Cw1, Cb1, bP, bC);
    cudaMemsetAsync(cs, 0, (size_t)Nn * sizeof(int));
    cudaMemsetAsync(cp, 0, (size_t)Nn * sizeof(int));
    count_kernel<<<(E + 255) / 256, 256>>>(self_idx, parent_idx, cs, cp, E);

    mlp_v_kernel<<<(Nn + 63) / 64, 256, SMEM_V>>>(batch_token, Vw1, Vb1, Vw2, Vb2, hid, Nn);

    for (int hop = 0; hop < 3; hop++) {
        cudaMemsetAsync(sp, 0, (size_t)Nn * 128 * sizeof(float));
        cudaMemsetAsync(sc, 0, (size_t)Nn * 128 * sizeof(float));
        edge_kernel<<<(E + 63) / 64, 256, SMEM_E>>>(hid, self_idx, parent_idx,
                                                    Pw1, Pw2, Pb2, Cw1, Cw2, Cb2,
                                                    bP, bC, sp, sc, E);
        float* o = (hop == 2) ? (float*)d_out : hid;
        node_kernel<<<(Nn + 63) / 64, 256, SMEM_N>>>(hid, sp, sc, cs, cp,
                                                     root_mask, leaf_mask, start_tok, end_tok,
                                                     Aw1, Ab1, Aw2, Ab2, o, Nn);
    }
}

// round 5
// speedup vs baseline: 1.1178x; 1.1178x over previous
#include <cuda_runtime.h>
#include <cstdint>

#define MAXN 250000
#define DD 128
#define HH 256

// ---------------- scratch (device globals: no allocations allowed) ----------------
__device__ float g_hidden[MAXN * DD];
__device__ float g_sp[MAXN * DD];
__device__ float g_sc[MAXN * DD];
__device__ int   g_cnt_self[MAXN];
__device__ int   g_cnt_par[MAXN];
__device__ float g_biasP[HH];
__device__ float g_biasC[HH];

// vectorized global reduction (sm_90+)
__device__ __forceinline__ void red_add_v4(float* p, float x, float y, float z, float w) {
    asm volatile("red.global.add.v4.f32 [%0], {%1,%2,%3,%4};"
                 :: "l"(p), "f"(x), "f"(y), "f"(z), "f"(w) : "memory");
}

// ---------------- small precompute: edge vectors -> folded layer-1 biases ----------
__global__ void precompute_kernel(const float* __restrict__ Ew1, const float* __restrict__ Eb1,
                                  const float* __restrict__ Ew2, const float* __restrict__ Eb2,
                                  const float* __restrict__ Pw1, const float* __restrict__ Pb1,
                                  const float* __restrict__ Cw1, const float* __restrict__ Cb1,
                                  float* __restrict__ biasP, float* __restrict__ biasC) {
    __shared__ float hin[HH], hout[HH], ein[DD], eout[DD];
    int t = threadIdx.x;
    if (t < HH) {
        hin[t]  = fmaxf(Ew1[t] + Eb1[t], 0.f);  // x = 1
        hout[t] = fmaxf(Eb1[t], 0.f);           // x = 0
    }
    __syncthreads();
    if (t < DD) {
        float si = Eb2[t], so = Eb2[t];
        for (int j = 0; j < HH; j++) {
            si += hin[j]  * Ew2[j * DD + t];
            so += hout[j] * Ew2[j * DD + t];
        }
        ein[t]  = fmaxf(si, 0.f);
        eout[t] = fmaxf(so, 0.f);
    }
    __syncthreads();
    if (t < HH) {
        float bp = Pb1[t], bc = Cb1[t];
        for (int d = 0; d < DD; d++) {
            bp += eout[d] * Pw1[(2 * DD + d) * HH + t];
            bc += ein[d]  * Cw1[(2 * DD + d) * HH + t];
        }
        biasP[t] = bp;
        biasC[t] = bc;
    }
}

__global__ void count_kernel(const int* __restrict__ si, const int* __restrict__ pi,
                             int* __restrict__ cs, int* __restrict__ cp, int E) {
    int e = blockIdx.x * blockDim.x + threadIdx.x;
    if (e < E) {
        atomicAdd(&cs[si[e]], 1);
        atomicAdd(&cp[pi[e]], 1);
    }
}

// ---------------- fused 2-layer MLP core ----------------
// Block: 256 threads, BM = 64 rows.
// Layer 1: T[64][256] = relu(As[64][K1] @ W1 + bias1)   (8x8 microtile, 32x8 thread grid)
// Layer 2: acc2[64][128] = As2 @ W2 + b2                (8x4 microtile)  (relu by caller)
// Weights streamed from L2 in 32-row tiles, register->smem double buffered.
// A-fragments loaded as float4 along k (k chunked by 4) to minimize LDS issue slots.
template <int K1>
__device__ __forceinline__ void fused_mlp(
    const float* __restrict__ As, float* __restrict__ Ts, float* __restrict__ Ws,
    const float* __restrict__ w1s0, const float* __restrict__ w1s1, const float* __restrict__ w1s2,
    const float* __restrict__ bias1, const float* __restrict__ w2, const float* __restrict__ b2,
    float acc2[8][4]) {
    const int tid = threadIdx.x;
    const int tx = tid & 31, ty = tid >> 5;
    const int n0 = tx * 8, m0 = ty * 8;
    constexpr int T = K1 / 32;

    float acc[8][8];
#pragma unroll
    for (int j = 0; j < 8; j++) {
        float b = bias1[n0 + j];
#pragma unroll
        for (int i = 0; i < 8; i++) acc[i][j] = b;
    }

    __syncthreads();  // As visible to all; Ws free (prior phase done)
    {
        const float* src = w1s0;
#pragma unroll
        for (int i = 0; i < 8; i++) {
            int f = tid + i * 256;
            *(float4*)(Ws + f * 4) = *(const float4*)(src + f * 4);
        }
    }
    __syncthreads();
    int buf = 0;
    for (int t = 0; t < T; t++) {
        float4 pre[8];
        if (t + 1 < T) {
            int k0n = (t + 1) * 32;
            const float* src = (k0n < 128) ? (w1s0 + k0n * 256)
                             : (k0n < 256) ? (w1s1 + (k0n - 128) * 256)
                                           : (w1s2 + (k0n - 256) * 256);
#pragma unroll
            for (int i = 0; i < 8; i++) {
                int f = tid + i * 256;
                pre[i] = *(const float4*)(src + f * 4);
            }
        }
        const float* W = Ws + buf * 8192;
        const float* Abase = As + m0 * K1 + t * 32;
#pragma unroll
        for (int k4 = 0; k4 < 8; k4++) {
            float4 av[8];
#pragma unroll
            for (int i = 0; i < 8; i++)
                av[i] = *(const float4*)(Abase + i * K1 + k4 * 4);
            const float* Wk = W + k4 * 4 * 256;
#pragma unroll
            for (int kk = 0; kk < 4; kk++) {
                float4 b0 = *(const float4*)(Wk + kk * 256 + n0);
                float4 b1 = *(const float4*)(Wk + kk * 256 + n0 + 4);
                float bb[8] = {b0.x, b0.y, b0.z, b0.w, b1.x, b1.y, b1.z, b1.w};
#pragma unroll
                for (int i = 0; i < 8; i++) {
                    float a = (&av[i].x)[kk];
#pragma unroll
                    for (int j = 0; j < 8; j++) acc[i][j] = fmaf(a, bb[j], acc[i][j]);
                }
            }
        }
        if (t + 1 < T) {
#pragma unroll
            for (int i = 0; i < 8; i++) {
                int f = tid + i * 256;
                *(float4*)(Ws + (buf ^ 1) * 8192 + f * 4) = pre[i];
            }
            __syncthreads();
            buf ^= 1;
        }
    }
    // relu -> Ts
#pragma unroll
    for (int i = 0; i < 8; i++) {
        float4 o0, o1;
        o0.x = fmaxf(acc[i][0], 0.f); o0.y = fmaxf(acc[i][1], 0.f);
        o0.z = fmaxf(acc[i][2], 0.f); o0.w = fmaxf(acc[i][3], 0.f);
        o1.x = fmaxf(acc[i][4], 0.f); o1.y = fmaxf(acc[i][5], 0.f);
        o1.z = fmaxf(acc[i][6], 0.f); o1.w = fmaxf(acc[i][7], 0.f);
        *(float4*)(Ts + (m0 + i) * 256 + n0) = o0;
        *(float4*)(Ts + (m0 + i) * 256 + n0 + 4) = o1;
    }
    __syncthreads();  // Ts ready; all layer-1 Ws reads done

    // ---- layer 2 ----
    const int n2 = (tid & 31) * 4, m2 = (tid >> 5) * 8;
#pragma unroll
    for (int j = 0; j < 4; j++) {
        float b = b2[n2 + j];
#pragma unroll
        for (int i = 0; i < 8; i++) acc2[i][j] = b;
    }
    {
#pragma unroll
        for (int i = 0; i < 4; i++) {
            int f = tid + i * 256;
            *(float4*)(Ws + f * 4) = *(const float4*)(w2 + f * 4);
        }
    }
    __syncthreads();
    buf = 0;
    for (int t = 0; t < 8; t++) {
        float4 pre[4];
        if (t + 1 < 8) {
            const float* src = w2 + (t + 1) * 32 * 128;
#pragma unroll
            for (int i = 0; i < 4; i++) {
                int f = tid + i * 256;
                pre[i] = *(const float4*)(src + f * 4);
            }
        }
        const float* W = Ws + buf * 8192;
        const float* Tbase = Ts + m2 * 256 + t * 32;
#pragma unroll
        for (int k4 = 0; k4 < 8; k4++) {
            float4 av[8];
#pragma unroll
            for (int i = 0; i < 8; i++)
                av[i] = *(const float4*)(Tbase + i * 256 + k4 * 4);
            const float* Wk = W + k4 * 4 * 128;
#pragma unroll
            for (int kk = 0; kk < 4; kk++) {
                float4 bv = *(const float4*)(Wk + kk * 128 + n2);
                float bb[4] = {bv.x, bv.y, bv.z, bv.w};
#pragma unroll
                for (int i = 0; i < 8; i++) {
                    float a = (&av[i].x)[kk];
#pragma unroll
                    for (int j = 0; j < 4; j++) acc2[i][j] = fmaf(a, bb[j], acc2[i][j]);
                }
            }
        }
        if (t + 1 < 8) {
#pragma unroll
            for (int i = 0; i < 4; i++) {
                int f = tid + i * 256;
                *(float4*)(Ws + (buf ^ 1) * 8192 + f * 4) = pre[i];
            }
            __syncthreads();
            buf ^= 1;
        }
    }
}

// ---------------- kernel: hidden = MLP_V(batch_token) ----------------
// smem: As 64*128 | Ts 64*256 | Ws 2*32*256   = 40960 floats = 160 KB
__global__ __launch_bounds__(256, 1) void mlp_v_kernel(
    const float* __restrict__ x,
    const float* __restrict__ Vw1, const float* __restrict__ Vb1,
    const float* __restrict__ Vw2, const float* __restrict__ Vb2,
    float* __restrict__ hidden, int Nn) {
    extern __shared__ float sm[];
    float* As = sm;
    float* Ts = As + 64 * 128;
    float* Ws = Ts + 64 * 256;
    const int tid = threadIdx.x, lane = tid & 31;
    const int i0 = blockIdx.x * 64;
    for (int r = tid >> 5; r < 64; r += 8) {
        int i = i0 + r;
        float4 v = make_float4(0.f, 0.f, 0.f, 0.f);
        if (i < Nn) v = *(const float4*)(x + (long)i * 128 + lane * 4);
        *(float4*)(As + r * 128 + lane * 4) = v;
    }
    float acc2[8][4];
    fused_mlp<128>(As, Ts, Ws, Vw1, Vw1, Vw1, Vb1, Vw2, Vb2, acc2);
    const int n2 = (tid & 31) * 4, m2 = (tid >> 5) * 8;
#pragma unroll
    for (int i = 0; i < 8; i++) {
        int node = i0 + m2 + i;
        if (node < Nn) {
            float4 o;
            o.x = fmaxf(acc2[i][0], 0.f);
            o.y = fmaxf(acc2[i][1], 0.f);
            o.z = fmaxf(acc2[i][2], 0.f);
            o.w = fmaxf(acc2[i][3], 0.f);
            *(float4*)(hidden + (long)node * 128 + n2) = o;
        }
    }
}

// ---------------- kernel: per-edge MLP_P and MLP_C + scatter-sum ----------------
// smem: As 64*256 | Ts 64*256 | Ws 2*32*256 | idx 2*64 ints  = 197120 B
__global__ __launch_bounds__(256, 1) void edge_kernel(
    const float* __restrict__ hidden,
    const int* __restrict__ self_idx, const int* __restrict__ parent_idx,
    const float* __restrict__ Pw1, const float* __restrict__ Pw2, const float* __restrict__ Pb2,
    const float* __restrict__ Cw1, const float* __restrict__ Cw2, const float* __restrict__ Cb2,
    const float* __restrict__ biasP, const float* __restrict__ biasC,
    float* __restrict__ sp, float* __restrict__ sc, int E) {
    extern __shared__ float sm[];
    float* As = sm;            // [64][256]: [0:128]=parent, [128:256]=self
    float* Ts = As + 64 * 256;
    float* Ws = Ts + 64 * 256;
    int* sIdx = (int*)(Ws + 16384);
    int* pIdx = sIdx + 64;
    const int tid = threadIdx.x, lane = tid & 31;
    const int e0 = blockIdx.x * 64;
    if (tid < 64) {
        int e = e0 + tid;
        sIdx[tid] = (e < E) ? self_idx[e] : -1;
        pIdx[tid] = (e < E) ? parent_idx[e] : -1;
    }
    __syncthreads();
    for (int r = tid >> 5; r < 128; r += 8) {
        int er = r & 63;
        bool isPar = r < 64;
        int idx = isPar ? pIdx[er] : sIdx[er];
        float4 v = make_float4(0.f, 0.f, 0.f, 0.f);
        if (idx >= 0) v = *(const float4*)(hidden + (long)idx * 128 + lane * 4);
        *(float4*)(As + er * 256 + (isPar ? 0 : 128) + lane * 4) = v;
    }
    float acc2[8][4];
    const int n2 = (tid & 31) * 4, m2 = (tid >> 5) * 8;

    // MLP_P: inp = [parent | self] -> Pw1 rows [0:128], [128:256]; scatter by self_idx
    fused_mlp<256>(As, Ts, Ws, Pw1, Pw1 + 128 * 256, Pw1, biasP, Pw2, Pb2, acc2);
#pragma unroll
    for (int i = 0; i < 8; i++) {
        int idx = sIdx[m2 + i];
        if (idx >= 0) {
            red_add_v4(sp + (long)idx * 128 + n2,
                       fmaxf(acc2[i][0], 0.f), fmaxf(acc2[i][1], 0.f),
                       fmaxf(acc2[i][2], 0.f), fmaxf(acc2[i][3], 0.f));
        }
    }
    // MLP_C: inp = [self | parent] -> swap weight halves; scatter by parent_idx
    fused_mlp<256>(As, Ts, Ws, Cw1 + 128 * 256, Cw1, Cw1, biasC, Cw2, Cb2, acc2);
#pragma unroll
    for (int i = 0; i < 8; i++) {
        int idx = pIdx[m2 + i];
        if (idx >= 0) {
            red_add_v4(sc + (long)idx * 128 + n2,
                       fmaxf(acc2[i][0], 0.f), fmaxf(acc2[i][1], 0.f),
                       fmaxf(acc2[i][2], 0.f), fmaxf(acc2[i][3], 0.f));
        }
    }
}

// ---------------- kernel: node aggregation (mean + masks + MLP_A + residual) ------
// smem: As 64*384 | Ts 64*256 | Ws 2*32*256  = 229376 B
__global__ __launch_bounds__(256, 1) void node_kernel(
    const float* __restrict__ hidden,
    const float* __restrict__ sp, const float* __restrict__ sc,
    const int* __restrict__ cntS, const int* __restrict__ cntP,
    const float* __restrict__ root_mask, const float* __restrict__ leaf_mask,
    const float* __restrict__ start_tok, const float* __restrict__ end_tok,
    const float* __restrict__ Aw1, const float* __restrict__ Ab1,
    const float* __restrict__ Aw2, const float* __restrict__ Ab2,
    float* __restrict__ out, int Nn) {
    extern __shared__ float sm[];
    float* As = sm;            // [64][384]: hidden | S_p | S_c
    float* Ts = As + 64 * 384;
    float* Ws = Ts + 64 * 256;
    const int tid = threadIdx.x, lane = tid & 31;
    const int i0 = blockIdx.x * 64;
    float4 st = *(const float4*)(start_tok + lane * 4);
    float4 et = *(const float4*)(end_tok + lane * 4);
    for (int r = tid >> 5; r < 64; r += 8) {
        int i = i0 + r;
        float4 h = make_float4(0.f, 0.f, 0.f, 0.f), spv = h, scv = h;
        if (i < Nn) {
            h = *(const float4*)(hidden + (long)i * 128 + lane * 4);
            int csv = cntS[i]; if (csv < 1) csv = 1;
            int cpv = cntP[i]; if (cpv < 1) cpv = 1;
            float invS = 1.0f / (float)csv;
            float invP = 1.0f / (float)cpv;
            float rm = root_mask[i], lm = leaf_mask[i];
            spv = *(const float4*)(sp + (long)i * 128 + lane * 4);
            scv = *(const float4*)(sc + (long)i * 128 + lane * 4);
            spv.x = spv.x * invS + rm * st.x; spv.y = spv.y * invS + rm * st.y;
            spv.z = spv.z * invS + rm * st.z; spv.w = spv.w * invS + rm * st.w;
            scv.x = scv.x * invP + lm * et.x; scv.y = scv.y * invP + lm * et.y;
            scv.z = scv.z * invP + lm * et.z; scv.w = scv.w * invP + lm * et.w;
        }
        *(float4*)(As + r * 384 + lane * 4) = h;
        *(float4*)(As + r * 384 + 128 + lane * 4) = spv;
        *(float4*)(As + r * 384 + 256 + lane * 4) = scv;
    }
    float acc2[8][4];
    fused_mlp<384>(As, Ts, Ws, Aw1, Aw1 + 128 * 256, Aw1 + 256 * 256, Ab1, Aw2, Ab2, acc2);
    const int n2 = (tid & 31) * 4, m2 = (tid >> 5) * 8;
#pragma unroll
    for (int i = 0; i < 8; i++) {
        int node = i0 + m2 + i;
        if (node < Nn) {
            int r = m2 + i;
            float4 o;
            o.x = As[r * 384 + n2 + 0] + fmaxf(acc2[i][0], 0.f);
            o.y = As[r * 384 + n2 + 1] + fmaxf(acc2[i][1], 0.f);
            o.z = As[r * 384 + n2 + 2] + fmaxf(acc2[i][2], 0.f);
            o.w = As[r * 384 + n2 + 3] + fmaxf(acc2[i][3], 0.f);
            *(float4*)(out + (long)node * 128 + n2) = o;
        }
    }
}

// ---------------- host launch ----------------
extern "C" void kernel_launch(void* const* d_in, const int* in_sizes, int n_in,
                              void* d_out, int out_size) {
    const float* batch_token = (const float*)d_in[0];
    const int*   self_idx    = (const int*)d_in[1];
    const int*   parent_idx  = (const int*)d_in[2];
    const float* root_mask   = (const float*)d_in[3];
    const float* leaf_mask   = (const float*)d_in[4];
    const float* start_tok   = (const float*)d_in[5];
    const float* end_tok     = (const float*)d_in[6];
    const float* Vw1 = (const float*)d_in[7];
    const float* Vb1 = (const float*)d_in[8];
    const float* Vw2 = (const float*)d_in[9];
    const float* Vb2 = (const float*)d_in[10];
    const float* Ew1 = (const float*)d_in[11];
    const float* Eb1 = (const float*)d_in[12];
    const float* Ew2 = (const float*)d_in[13];
    const float* Eb2 = (const float*)d_in[14];
    const float* Pw1 = (const float*)d_in[15];
    const float* Pb1 = (const float*)d_in[16];
    const float* Pw2 = (const float*)d_in[17];
    const float* Pb2 = (const float*)d_in[18];
    const float* Cw1 = (const float*)d_in[19];
    const float* Cb1 = (const float*)d_in[20];
    const float* Cw2 = (const float*)d_in[21];
    const float* Cb2 = (const float*)d_in[22];
    const float* Aw1 = (const float*)d_in[23];
    const float* Ab1 = (const float*)d_in[24];
    const float* Aw2 = (const float*)d_in[25];
    const float* Ab2 = (const float*)d_in[26];

    const int Nn = in_sizes[0] / 128;
    const int E  = in_sizes[1];

    float *hid, *sp, *sc, *bP, *bC;
    int *cs, *cp;
    cudaGetSymbolAddress((void**)&hid, g_hidden);
    cudaGetSymbolAddress((void**)&sp,  g_sp);
    cudaGetSymbolAddress((void**)&sc,  g_sc);
    cudaGetSymbolAddress((void**)&cs,  g_cnt_self);
    cudaGetSymbolAddress((void**)&cp,  g_cnt_par);
    cudaGetSymbolAddress((void**)&bP,  g_biasP);
    cudaGetSymbolAddress((void**)&bC,  g_biasC);

    const int SMEM_V = (64 * 128 + 64 * 256 + 2 * 32 * 256) * 4;              // 163840
    const int SMEM_E = (64 * 256 + 64 * 256 + 2 * 32 * 256) * 4 + 2 * 64 * 4; // 197120
    const int SMEM_N = (64 * 384 + 64 * 256 + 2 * 32 * 256) * 4;              // 229376
    cudaFuncSetAttribute(mlp_v_kernel, cudaFuncAttributeMaxDynamicSharedMemorySize, SMEM_V);
    cudaFuncSetAttribute(edge_kernel,  cudaFuncAttributeMaxDynamicSharedMemorySize, SMEM_E);
    cudaFuncSetAttribute(node_kernel,  cudaFuncAttributeMaxDynamicSharedMemorySize, SMEM_N);

    precompute_kernel<<<1, 256>>>(Ew1, Eb1, Ew2, Eb2, Pw1, Pb1, Cw1, Cb1, bP, bC);
    cudaMemsetAsync(cs, 0, (size_t)Nn * sizeof(int));
    cudaMemsetAsync(cp, 0, (size_t)Nn * sizeof(int));
    count_kernel<<<(E + 255) / 256, 256>>>(self_idx, parent_idx, cs, cp, E);

    mlp_v_kernel<<<(Nn + 63) / 64, 256, SMEM_V>>>(batch_token, Vw1, Vb1, Vw2, Vb2, hid, Nn);

    for (int hop = 0; hop < 3; hop++) {
        cudaMemsetAsync(sp, 0, (size_t)Nn * 128 * sizeof(float));
        cudaMemsetAsync(sc, 0, (size_t)Nn * 128 * sizeof(float));
        edge_kernel<<<(E + 63) / 64, 256, SMEM_E>>>(hid, self_idx, parent_idx,
                                                    Pw1, Pw2, Pb2, Cw1, Cw2, Cb2,
                                                    bP, bC, sp, sc, E);
        float* o = (hop == 2) ? (float*)d_out : hid;
        node_kernel<<<(Nn + 63) / 64, 256, SMEM_N>>>(hid, sp, sc, cs, cp,
                                                     root_mask, leaf_mask, start_tok, end_tok,
                                                     Aw1, Ab1, Aw2, Ab2, o, Nn);
    }
}

// round 6
// speedup vs baseline: 1.1228x; 1.0045x over previous
#include <cuda_runtime.h>
#include <cstdint>

#define MAXN 250000
#define DD 128
#define HH 256

// ---------------- scratch (device globals: no allocations allowed) ----------------
__device__ float g_hidden[MAXN * DD];
__device__ float g_sp[MAXN * DD];
__device__ float g_sc[MAXN * DD];
__device__ int   g_cnt_self[MAXN];
__device__ int   g_cnt_par[MAXN];
__device__ float g_biasP[HH];
__device__ float g_biasC[HH];

// vectorized global reduction (sm_90+)
__device__ __forceinline__ void red_add_v4(float* p, float x, float y, float z, float w) {
    asm volatile("red.global.add.v4.f32 [%0], {%1,%2,%3,%4};"
                 :: "l"(p), "f"(x), "f"(y), "f"(z), "f"(w) : "memory");
}

// ---------------- small precompute: edge vectors -> folded layer-1 biases ----------
__global__ void precompute_kernel(const float* __restrict__ Ew1, const float* __restrict__ Eb1,
                                  const float* __restrict__ Ew2, const float* __restrict__ Eb2,
                                  const float* __restrict__ Pw1, const float* __restrict__ Pb1,
                                  const float* __restrict__ Cw1, const float* __restrict__ Cb1,
                                  float* __restrict__ biasP, float* __restrict__ biasC) {
    __shared__ float hin[HH], hout[HH], ein[DD], eout[DD];
    int t = threadIdx.x;
    if (t < HH) {
        hin[t]  = fmaxf(Ew1[t] + Eb1[t], 0.f);  // x = 1
        hout[t] = fmaxf(Eb1[t], 0.f);           // x = 0
    }
    __syncthreads();
    if (t < DD) {
        float si = Eb2[t], so = Eb2[t];
        for (int j = 0; j < HH; j++) {
            si += hin[j]  * Ew2[j * DD + t];
            so += hout[j] * Ew2[j * DD + t];
        }
        ein[t]  = fmaxf(si, 0.f);
        eout[t] = fmaxf(so, 0.f);
    }
    __syncthreads();
    if (t < HH) {
        float bp = Pb1[t], bc = Cb1[t];
        for (int d = 0; d < DD; d++) {
            bp += eout[d] * Pw1[(2 * DD + d) * HH + t];
            bc += ein[d]  * Cw1[(2 * DD + d) * HH + t];
        }
        biasP[t] = bp;
        biasC[t] = bc;
    }
}

__global__ void count_kernel(const int* __restrict__ si, const int* __restrict__ pi,
                             int* __restrict__ cs, int* __restrict__ cp, int E) {
    int e = blockIdx.x * blockDim.x + threadIdx.x;
    if (e < E) {
        atomicAdd(&cs[si[e]], 1);
        atomicAdd(&cp[pi[e]], 1);
    }
}

// ---------------- fused 2-layer MLP core ----------------
// Block: 256 threads, BM = 64 rows.
// Layer 1: T[64][256] = relu(As[64][K1] @ W1 + bias1)   (8x8 microtile, 32x8 thread grid)
// Layer 2: acc2[64][128] = As2 @ W2 + b2                (8x4 microtile)  (relu by caller)
// Weights streamed from L2 in 32-row tiles, register->smem double buffered.
// A-fragments loaded as float4 along k (k chunked by 4) to minimize LDS issue slots.
template <int K1>
__device__ __forceinline__ void fused_mlp(
    const float* __restrict__ As, float* __restrict__ Ts, float* __restrict__ Ws,
    const float* __restrict__ w1s0, const float* __restrict__ w1s1, const float* __restrict__ w1s2,
    const float* __restrict__ bias1, const float* __restrict__ w2, const float* __restrict__ b2,
    float acc2[8][4]) {
    const int tid = threadIdx.x;
    const int tx = tid & 31, ty = tid >> 5;
    const int n0 = tx * 8, m0 = ty * 8;
    constexpr int T = K1 / 32;

    float acc[8][8];
#pragma unroll
    for (int j = 0; j < 8; j++) {
        float b = bias1[n0 + j];
#pragma unroll
        for (int i = 0; i < 8; i++) acc[i][j] = b;
    }

    __syncthreads();  // As visible to all; Ws free (prior phase done)
    {
        const float* src = w1s0;
#pragma unroll
        for (int i = 0; i < 8; i++) {
            int f = tid + i * 256;
            *(float4*)(Ws + f * 4) = *(const float4*)(src + f * 4);
        }
    }
    __syncthreads();
    int buf = 0;
    for (int t = 0; t < T; t++) {
        float4 pre[8];
        if (t + 1 < T) {
            int k0n = (t + 1) * 32;
            const float* src = (k0n < 128) ? (w1s0 + k0n * 256)
                             : (k0n < 256) ? (w1s1 + (k0n - 128) * 256)
                                           : (w1s2 + (k0n - 256) * 256);
#pragma unroll
            for (int i = 0; i < 8; i++) {
                int f = tid + i * 256;
                pre[i] = *(const float4*)(src + f * 4);
            }
        }
        const float* W = Ws + buf * 8192;
        const float* Abase = As + m0 * K1 + t * 32;
#pragma unroll
        for (int k4 = 0; k4 < 8; k4++) {
            float4 av[8];
#pragma unroll
            for (int i = 0; i < 8; i++)
                av[i] = *(const float4*)(Abase + i * K1 + k4 * 4);
            const float* Wk = W + k4 * 4 * 256;
#pragma unroll
            for (int kk = 0; kk < 4; kk++) {
                float4 b0 = *(const float4*)(Wk + kk * 256 + n0);
                float4 b1 = *(const float4*)(Wk + kk * 256 + n0 + 4);
                float bb[8] = {b0.x, b0.y, b0.z, b0.w, b1.x, b1.y, b1.z, b1.w};
#pragma unroll
                for (int i = 0; i < 8; i++) {
                    float a = (&av[i].x)[kk];
#pragma unroll
                    for (int j = 0; j < 8; j++) acc[i][j] = fmaf(a, bb[j], acc[i][j]);
                }
            }
        }
        if (t + 1 < T) {
#pragma unroll
            for (int i = 0; i < 8; i++) {
                int f = tid + i * 256;
                *(float4*)(Ws + (buf ^ 1) * 8192 + f * 4) = pre[i];
            }
            __syncthreads();
            buf ^= 1;
        }
    }
    // relu -> Ts
#pragma unroll
    for (int i = 0; i < 8; i++) {
        float4 o0, o1;
        o0.x = fmaxf(acc[i][0], 0.f); o0.y = fmaxf(acc[i][1], 0.f);
        o0.z = fmaxf(acc[i][2], 0.f); o0.w = fmaxf(acc[i][3], 0.f);
        o1.x = fmaxf(acc[i][4], 0.f); o1.y = fmaxf(acc[i][5], 0.f);
        o1.z = fmaxf(acc[i][6], 0.f); o1.w = fmaxf(acc[i][7], 0.f);
        *(float4*)(Ts + (m0 + i) * 256 + n0) = o0;
        *(float4*)(Ts + (m0 + i) * 256 + n0 + 4) = o1;
    }
    __syncthreads();  // Ts ready; all layer-1 Ws reads done

    // ---- layer 2 ----
    const int n2 = (tid & 31) * 4, m2 = (tid >> 5) * 8;
#pragma unroll
    for (int j = 0; j < 4; j++) {
        float b = b2[n2 + j];
#pragma unroll
        for (int i = 0; i < 8; i++) acc2[i][j] = b;
    }
    {
#pragma unroll
        for (int i = 0; i < 4; i++) {
            int f = tid + i * 256;
            *(float4*)(Ws + f * 4) = *(const float4*)(w2 + f * 4);
        }
    }
    __syncthreads();
    buf = 0;
    for (int t = 0; t < 8; t++) {
        float4 pre[4];
        if (t + 1 < 8) {
            const float* src = w2 + (t + 1) * 32 * 128;
#pragma unroll
            for (int i = 0; i < 4; i++) {
                int f = tid + i * 256;
                pre[i] = *(const float4*)(src + f * 4);
            }
        }
        const float* W = Ws + buf * 8192;
        const float* Tbase = Ts + m2 * 256 + t * 32;
#pragma unroll
        for (int k4 = 0; k4 < 8; k4++) {
            float4 av[8];
#pragma unroll
            for (int i = 0; i < 8; i++)
                av[i] = *(const float4*)(Tbase + i * 256 + k4 * 4);
            const float* Wk = W + k4 * 4 * 128;
#pragma unroll
            for (int kk = 0; kk < 4; kk++) {
                float4 bv = *(const float4*)(Wk + kk * 128 + n2);
                float bb[4] = {bv.x, bv.y, bv.z, bv.w};
#pragma unroll
                for (int i = 0; i < 8; i++) {
                    float a = (&av[i].x)[kk];
#pragma unroll
                    for (int j = 0; j < 4; j++) acc2[i][j] = fmaf(a, bb[j], acc2[i][j]);
                }
            }
        }
        if (t + 1 < 8) {
#pragma unroll
            for (int i = 0; i < 4; i++) {
                int f = tid + i * 256;
                *(float4*)(Ws + (buf ^ 1) * 8192 + f * 4) = pre[i];
            }
            __syncthreads();
            buf ^= 1;
        }
    }
}

// ---------------- kernel: hidden = MLP_V(batch_token) ----------------
// smem: As 64*128 | Ts 64*256 | Ws 2*32*256   = 40960 floats = 160 KB
__global__ __launch_bounds__(256, 1) void mlp_v_kernel(
    const float* __restrict__ x,
    const float* __restrict__ Vw1, const float* __restrict__ Vb1,
    const float* __restrict__ Vw2, const float* __restrict__ Vb2,
    float* __restrict__ hidden, int Nn) {
    extern __shared__ float sm[];
    float* As = sm;
    float* Ts = As + 64 * 128;
    float* Ws = Ts + 64 * 256;
    const int tid = threadIdx.x, lane = tid & 31;
    const int i0 = blockIdx.x * 64;
    for (int r = tid >> 5; r < 64; r += 8) {
        int i = i0 + r;
        float4 v = make_float4(0.f, 0.f, 0.f, 0.f);
        if (i < Nn) v = *(const float4*)(x + (long)i * 128 + lane * 4);
        *(float4*)(As + r * 128 + lane * 4) = v;
    }
    float acc2[8][4];
    fused_mlp<128>(As, Ts, Ws, Vw1, Vw1, Vw1, Vb1, Vw2, Vb2, acc2);
    const int n2 = (tid & 31) * 4, m2 = (tid >> 5) * 8;
#pragma unroll
    for (int i = 0; i < 8; i++) {
        int node = i0 + m2 + i;
        if (node < Nn) {
            float4 o;
            o.x = fmaxf(acc2[i][0], 0.f);
            o.y = fmaxf(acc2[i][1], 0.f);
            o.z = fmaxf(acc2[i][2], 0.f);
            o.w = fmaxf(acc2[i][3], 0.f);
            *(float4*)(hidden + (long)node * 128 + n2) = o;
        }
    }
}

// ---------------- kernel: per-edge MLP_P and MLP_C + scatter-sum ----------------
// smem: As 64*256 | Ts 64*256 | Ws 2*32*256 | idx 2*64 ints  = 197120 B
__global__ __launch_bounds__(256, 1) void edge_kernel(
    const float* __restrict__ hidden,
    const int* __restrict__ self_idx, const int* __restrict__ parent_idx,
    const float* __restrict__ Pw1, const float* __restrict__ Pw2, const float* __restrict__ Pb2,
    const float* __restrict__ Cw1, const float* __restrict__ Cw2, const float* __restrict__ Cb2,
    const float* __restrict__ biasP, const float* __restrict__ biasC,
    float* __restrict__ sp, float* __restrict__ sc, int E) {
    extern __shared__ float sm[];
    float* As = sm;            // [64][256]: [0:128]=parent, [128:256]=self
    float* Ts = As + 64 * 256;
    float* Ws = Ts + 64 * 256;
    int* sIdx = (int*)(Ws + 16384);
    int* pIdx = sIdx + 64;
    const int tid = threadIdx.x, lane = tid & 31;
    const int e0 = blockIdx.x * 64;
    if (tid < 64) {
        int e = e0 + tid;
        sIdx[tid] = (e < E) ? self_idx[e] : -1;
        pIdx[tid] = (e < E) ? parent_idx[e] : -1;
    }
    __syncthreads();
    for (int r = tid >> 5; r < 128; r += 8) {
        int er = r & 63;
        bool isPar = r < 64;
        int idx = isPar ? pIdx[er] : sIdx[er];
        float4 v = make_float4(0.f, 0.f, 0.f, 0.f);
        if (idx >= 0) v = *(const float4*)(hidden + (long)idx * 128 + lane * 4);
        *(float4*)(As + er * 256 + (isPar ? 0 : 128) + lane * 4) = v;
    }
    float acc2[8][4];
    const int n2 = (tid & 31) * 4, m2 = (tid >> 5) * 8;

    // MLP_P: inp = [parent | self] -> Pw1 rows [0:128], [128:256]; scatter by self_idx
    fused_mlp<256>(As, Ts, Ws, Pw1, Pw1 + 128 * 256, Pw1, biasP, Pw2, Pb2, acc2);
#pragma unroll
    for (int i = 0; i < 8; i++) {
        int idx = sIdx[m2 + i];
        if (idx >= 0) {
            red_add_v4(sp + (long)idx * 128 + n2,
                       fmaxf(acc2[i][0], 0.f), fmaxf(acc2[i][1], 0.f),
                       fmaxf(acc2[i][2], 0.f), fmaxf(acc2[i][3], 0.f));
        }
    }
    // MLP_C: inp = [self | parent] -> swap weight halves; scatter by parent_idx
    fused_mlp<256>(As, Ts, Ws, Cw1 + 128 * 256, Cw1, Cw1, biasC, Cw2, Cb2, acc2);
#pragma unroll
    for (int i = 0; i < 8; i++) {
        int idx = pIdx[m2 + i];
        if (idx >= 0) {
            red_add_v4(sc + (long)idx * 128 + n2,
                       fmaxf(acc2[i][0], 0.f), fmaxf(acc2[i][1], 0.f),
                       fmaxf(acc2[i][2], 0.f), fmaxf(acc2[i][3], 0.f));
        }
    }
}

// ---------------- kernel: node aggregation (mean + masks + MLP_A + residual) ------
// smem: As 64*384 | Ts 64*256 | Ws 2*32*256  = 229376 B
__global__ __launch_bounds__(256, 1) void node_kernel(
    const float* __restrict__ hidden,
    const float* __restrict__ sp, const float* __restrict__ sc,
    const int* __restrict__ cntS, const int* __restrict__ cntP,
    const float* __restrict__ root_mask, const float* __restrict__ leaf_mask,
    const float* __restrict__ start_tok, const float* __restrict__ end_tok,
    const float* __restrict__ Aw1, const float* __restrict__ Ab1,
    const float* __restrict__ Aw2, const float* __restrict__ Ab2,
    float* __restrict__ out, int Nn) {
    extern __shared__ float sm[];
    float* As = sm;            // [64][384]: hidden | S_p | S_c
    float* Ts = As + 64 * 384;
    float* Ws = Ts + 64 * 256;
    const int tid = threadIdx.x, lane = tid & 31;
    const int i0 = blockIdx.x * 64;
    float4 st = *(const float4*)(start_tok + lane * 4);
    float4 et = *(const float4*)(end_tok + lane * 4);
    for (int r = tid >> 5; r < 64; r += 8) {
        int i = i0 + r;
        float4 h = make_float4(0.f, 0.f, 0.f, 0.f), spv = h, scv = h;
        if (i < Nn) {
            h = *(const float4*)(hidden + (long)i * 128 + lane * 4);
            int csv = cntS[i]; if (csv < 1) csv = 1;
            int cpv = cntP[i]; if (cpv < 1) cpv = 1;
            float invS = 1.0f / (float)csv;
            float invP = 1.0f / (float)cpv;
            float rm = root_mask[i], lm = leaf_mask[i];
            spv = *(const float4*)(sp + (long)i * 128 + lane * 4);
            scv = *(const float4*)(sc + (long)i * 128 + lane * 4);
            spv.x = spv.x * invS + rm * st.x; spv.y = spv.y * invS + rm * st.y;
            spv.z = spv.z * invS + rm * st.z; spv.w = spv.w * invS + rm * st.w;
            scv.x = scv.x * invP + lm * et.x; scv.y = scv.y * invP + lm * et.y;
            scv.z = scv.z * invP + lm * et.z; scv.w = scv.w * invP + lm * et.w;
        }
        *(float4*)(As + r * 384 + lane * 4) = h;
        *(float4*)(As + r * 384 + 128 + lane * 4) = spv;
        *(float4*)(As + r * 384 + 256 + lane * 4) = scv;
    }
    float acc2[8][4];
    fused_mlp<384>(As, Ts, Ws, Aw1, Aw1 + 128 * 256, Aw1 + 256 * 256, Ab1, Aw2, Ab2, acc2);
    const int n2 = (tid & 31) * 4, m2 = (tid >> 5) * 8;
#pragma unroll
    for (int i = 0; i < 8; i++) {
        int node = i0 + m2 + i;
        if (node < Nn) {
            int r = m2 + i;
            float4 o;
            o.x = As[r * 384 + n2 + 0] + fmaxf(acc2[i][0], 0.f);
            o.y = As[r * 384 + n2 + 1] + fmaxf(acc2[i][1], 0.f);
            o.z = As[r * 384 + n2 + 2] + fmaxf(acc2[i][2], 0.f);
            o.w = As[r * 384 + n2 + 3] + fmaxf(acc2[i][3], 0.f);
            *(float4*)(out + (long)node * 128 + n2) = o;
        }
    }
}

// ---------------- host launch ----------------
extern "C" void kernel_launch(void* const* d_in, const int* in_sizes, int n_in,
                              void* d_out, int out_size) {
    const float* batch_token = (const float*)d_in[0];
    const int*   self_idx    = (const int*)d_in[1];
    const int*   parent_idx  = (const int*)d_in[2];
    const float* root_mask   = (const float*)d_in[3];
    const float* leaf_mask   = (const float*)d_in[4];
    const float* start_tok   = (const float*)d_in[5];
    const float* end_tok     = (const float*)d_in[6];
    const float* Vw1 = (const float*)d_in[7];
    const float* Vb1 = (const float*)d_in[8];
    const float* Vw2 = (const float*)d_in[9];
    const float* Vb2 = (const float*)d_in[10];
    const float* Ew1 = (const float*)d_in[11];
    const float* Eb1 = (const float*)d_in[12];
    const float* Ew2 = (const float*)d_in[13];
    const float* Eb2 = (const float*)d_in[14];
    const float* Pw1 = (const float*)d_in[15];
    const float* Pb1 = (const float*)d_in[16];
    const float* Pw2 = (const float*)d_in[17];
    const float* Pb2 = (const float*)d_in[18];
    const float* Cw1 = (const float*)d_in[19];
    const float* Cb1 = (const float*)d_in[20];
    const float* Cw2 = (const float*)d_in[21];
    const float* Cb2 = (const float*)d_in[22];
    const float* Aw1 = (const float*)d_in[23];
    const float* Ab1 = (const float*)d_in[24];
    const float* Aw2 = (const float*)d_in[25];
    const float* Ab2 = (const float*)d_in[26];

    const int Nn = in_sizes[0] / 128;
    const int E  = in_sizes[1];

    float *hid, *sp, *sc, *bP, *bC;
    int *cs, *cp;
    cudaGetSymbolAddress((void**)&hid, g_hidden);
    cudaGetSymbolAddress((void**)&sp,  g_sp);
    cudaGetSymbolAddress((void**)&sc,  g_sc);
    cudaGetSymbolAddress((void**)&cs,  g_cnt_self);
    cudaGetSymbolAddress((void**)&cp,  g_cnt_par);
    cudaGetSymbolAddress((void**)&bP,  g_biasP);
    cudaGetSymbolAddress((void**)&bC,  g_biasC);

    const int SMEM_V = (64 * 128 + 64 * 256 + 2 * 32 * 256) * 4;              // 163840
    const int SMEM_E = (64 * 256 + 64 * 256 + 2 * 32 * 256) * 4 + 2 * 64 * 4; // 197120
    const int SMEM_N = (64 * 384 + 64 * 256 + 2 * 32 * 256) * 4;              // 229376
    cudaFuncSetAttribute(mlp_v_kernel, cudaFuncAttributeMaxDynamicSharedMemorySize, SMEM_V);
    cudaFuncSetAttribute(edge_kernel,  cudaFuncAttributeMaxDynamicSharedMemorySize, SMEM_E);
    cudaFuncSetAttribute(node_kernel,  cudaFuncAttributeMaxDynamicSharedMemorySize, SMEM_N);

    precompute_kernel<<<1, 256>>>(Ew1, Eb1, Ew2, Eb2, Pw1, Pb1, Cw1, Cb1, bP, bC);
    cudaMemsetAsync(cs, 0, (size_t)Nn * sizeof(int));
    cudaMemsetAsync(cp, 0, (size_t)Nn * sizeof(int));
    count_kernel<<<(E + 255) / 256, 256>>>(self_idx, parent_idx, cs, cp, E);

    mlp_v_kernel<<<(Nn + 63) / 64, 256, SMEM_V>>>(batch_token, Vw1, Vb1, Vw2, Vb2, hid, Nn);

    for (int hop = 0; hop < 3; hop++) {
        cudaMemsetAsync(sp, 0, (size_t)Nn * 128 * sizeof(float));
        cudaMemsetAsync(sc, 0, (size_t)Nn * 128 * sizeof(float));
        edge_kernel<<<(E + 63) / 64, 256, SMEM_E>>>(hid, self_idx, parent_idx,
                                                    Pw1, Pw2, Pb2, Cw1, Cw2, Cb2,
                                                    bP, bC, sp, sc, E);
        float* o = (hop == 2) ? (float*)d_out : hid;
        node_kernel<<<(Nn + 63) / 64, 256, SMEM_N>>>(hid, sp, sc, cs, cp,
                                                     root_mask, leaf_mask, start_tok, end_tok,
                                                     Aw1, Ab1, Aw2, Ab2, o, Nn);
    }
}

// round 8
// speedup vs baseline: 2.1620x; 1.9255x over previous
#include <cuda_runtime.h>
#include <cstdint>

#define MAXN 250000
#define DD 128
#define HH 256

// ---------------- smem layout (byte offsets) ----------------
#define OFF_BIAS1 0        // 256 floats
#define OFF_BIAS2 1024     // 128 floats
#define OFF_AUX   1536     // kernel-specific (<= 4096 B)
#define OFF_BBUF  5632     // B double buffer (16 KB)
#define OFF_T     22016    // layer-2 A fragments (64 KB)
#define OFF_A     87552    // layer-1 A fragments (up to 96 KB)

#define SMEM_MLPV (OFF_A + 16 * 4 * 512)   // K=128
#define SMEM_EDGE (OFF_A + 32 * 4 * 512)   // K=256
#define SMEM_NODE (OFF_A + 48 * 4 * 512)   // K=384

// ---------------- device scratch ----------------
__device__ float g_hidden[MAXN * DD];
__device__ float g_sp[MAXN * DD];
__device__ float g_sc[MAXN * DD];
__device__ int   g_cnt_self[MAXN];
__device__ int   g_cnt_par[MAXN];
__device__ float g_biasP[HH];
__device__ float g_biasC[HH];

// weights in tf32 MMA-fragment order: word = ((k>>3)*NT + (n>>3))*64 + lane*2 + reg
__device__ __align__(16) uint32_t g_V1f[128 * 256];
__device__ __align__(16) uint32_t g_V2f[256 * 128];
__device__ __align__(16) uint32_t g_P1f[256 * 256];
__device__ __align__(16) uint32_t g_P2f[256 * 128];
__device__ __align__(16) uint32_t g_C1f[256 * 256];
__device__ __align__(16) uint32_t g_C2f[256 * 128];
__device__ __align__(16) uint32_t g_A1f[384 * 256];
__device__ __align__(16) uint32_t g_A2f[256 * 128];

// ---------------- helpers ----------------
__device__ __forceinline__ uint32_t tf32r(float x) {
    uint32_t y;
    asm("cvt.rna.tf32.f32 %0, %1;" : "=r"(y) : "f"(x));
    return y;
}
__device__ __forceinline__ uint32_t smem_u32(const void* p) {
    uint32_t a;
    asm("{ .reg .u64 t; cvta.to.shared.u64 t, %1; cvt.u32.u64 %0, t; }" : "=r"(a) : "l"(p));
    return a;
}
__device__ __forceinline__ void cpasync16(uint32_t dst, const void* src) {
    asm volatile("cp.async.ca.shared.global [%0], [%1], 16;" :: "r"(dst), "l"(src));
}
#define CP_COMMIT() asm volatile("cp.async.commit_group;")
#define CP_WAIT(n)  asm volatile("cp.async.wait_group %0;" :: "n"(n))

__device__ __forceinline__ void mma_tf32(float* d, const uint32_t* a, uint32_t b0, uint32_t b1) {
    asm volatile(
        "mma.sync.aligned.m16n8k8.row.col.f32.tf32.tf32.f32 "
        "{%0,%1,%2,%3}, {%4,%5,%6,%7}, {%8,%9}, {%0,%1,%2,%3};"
        : "+f"(d[0]), "+f"(d[1]), "+f"(d[2]), "+f"(d[3])
        : "r"(a[0]), "r"(a[1]), "r"(a[2]), "r"(a[3]), "r"(b0), "r"(b1));
}
__device__ __forceinline__ void red_add_v2(float* p, float x, float y) {
    asm volatile("red.global.add.v2.f32 [%0], {%1,%2};" :: "l"(p), "f"(x), "f"(y) : "memory");
}

// store float4 (row r, cols k0..k0+3, k0%4==0) into A-fragment layout at offA
__device__ __forceinline__ void stA4(char* sm, uint32_t offA, int kstep, int r, int k0, float4 v) {
    int tile = kstep * 4 + (r >> 4);
    int reg = ((k0 & 4) ? 2 : 0) + ((r & 8) ? 1 : 0);
    int la = (r & 7) * 4;
    uint32_t base = offA + (uint32_t)(tile * 128 + reg) * 4u + (uint32_t)la * 16u;
    *(uint32_t*)(sm + base)      = tf32r(v.x);
    *(uint32_t*)(sm + base + 16) = tf32r(v.y);
    *(uint32_t*)(sm + base + 32) = tf32r(v.z);
    *(uint32_t*)(sm + base + 48) = tf32r(v.w);
}
// store one element into layer-2 A-fragment region (OFF_T)
__device__ __forceinline__ void stT(char* sm, int r, int c, float v) {
    int tile = (c >> 3) * 4 + (r >> 4);
    int lane2 = (r & 7) * 4 + (c & 3);
    int reg2 = ((c & 4) ? 2 : 0) + ((r & 8) ? 1 : 0);
    *(uint32_t*)(sm + OFF_T + (uint32_t)(tile * 128 + lane2 * 4 + reg2) * 4u) = tf32r(v);
}

// ---------------- generic tf32 GEMM: 64 rows x (NT*8) cols, K = KS*8 ----------------
// 8 warps as 2(m) x 4(n); accum d[2][NTW][4]; B streamed via cp.async double buffer.
template <int KS, int NT, int NTW>
__device__ void gemm_tf32(char* sm, uint32_t sbase, uint32_t offA, int kXor,
                          const uint32_t* gB, float (&d)[2][NTW][4]) {
    const int tid = threadIdx.x, wid = tid >> 5, lane = tid & 31;
    const int warpM = wid >> 2, warpG = wid & 3;
    const int chunkB = NT * 64 * 4;              // bytes per k8 chunk
    const int cpN = chunkB / (16 * 256);         // cp.async per thread (2 or 1)
    {
        uint32_t dst = sbase + OFF_BBUF;
        const char* src = (const char*)gB;
#pragma unroll
        for (int i = 0; i < cpN; i++) {
            int f = tid + i * 256;
            cpasync16(dst + f * 16, src + f * 16);
        }
        CP_COMMIT();
    }
    for (int t = 0; t < KS; t++) {
        if (t + 1 < KS) {
            uint32_t dst = sbase + OFF_BBUF + ((t + 1) & 1) * chunkB;
            const char* src = (const char*)gB + (size_t)(t + 1) * chunkB;
#pragma unroll
            for (int i = 0; i < cpN; i++) {
                int f = tid + i * 256;
                cpasync16(dst + f * 16, src + f * 16);
            }
            CP_COMMIT();
            CP_WAIT(1);
        } else {
            CP_WAIT(0);
        }
        __syncthreads();
        int kst = t ^ kXor;
        uint32_t a[2][4];
#pragma unroll
        for (int mt = 0; mt < 2; mt++) {
            uint32_t addr = offA + (uint32_t)((kst * 4 + warpM * 2 + mt) * 128 + lane * 4) * 4u;
            uint4 va = *(const uint4*)(sm + addr);
            a[mt][0] = va.x; a[mt][1] = va.y; a[mt][2] = va.z; a[mt][3] = va.w;
        }
        uint32_t bbase = OFF_BBUF + (uint32_t)(t & 1) * chunkB;
#pragma unroll
        for (int j = 0; j < NTW; j++) {
            uint32_t baddr = bbase + (uint32_t)((warpG * NTW + j) * 64 + lane * 2) * 4u;
            uint2 vb = *(const uint2*)(sm + baddr);
            mma_tf32(d[0][j], a[0], vb.x, vb.y);
            mma_tf32(d[1][j], a[1], vb.x, vb.y);
        }
        __syncthreads();
    }
}

// layer-1 epilogue: relu(+bias1) -> layer-2 A fragments at OFF_T
__device__ void epilogue1_T(char* sm, float (&d)[2][8][4], const float* b1) {
    const int tid = threadIdx.x, wid = tid >> 5, lane = tid & 31;
    const int warpM = wid >> 2, warpG = wid & 3;
    const int g8 = lane >> 2, tig = lane & 3;
#pragma unroll
    for (int mt = 0; mt < 2; mt++) {
        int r0 = warpM * 32 + mt * 16 + g8;
#pragma unroll
        for (int j = 0; j < 8; j++) {
            int c = warpG * 64 + j * 8 + tig * 2;
            stT(sm, r0,     c,     fmaxf(d[mt][j][0] + b1[c],     0.f));
            stT(sm, r0,     c + 1, fmaxf(d[mt][j][1] + b1[c + 1], 0.f));
            stT(sm, r0 + 8, c,     fmaxf(d[mt][j][2] + b1[c],     0.f));
            stT(sm, r0 + 8, c + 1, fmaxf(d[mt][j][3] + b1[c + 1], 0.f));
        }
    }
    __syncthreads();
}

// ---------------- precompute kernels ----------------
__global__ void precompute_kernel(const float* __restrict__ Ew1, const float* __restrict__ Eb1,
                                  const float* __restrict__ Ew2, const float* __restrict__ Eb2,
                                  const float* __restrict__ Pw1, const float* __restrict__ Pb1,
                                  const float* __restrict__ Cw1, const float* __restrict__ Cb1,
                                  float* __restrict__ biasP, float* __restrict__ biasC) {
    __shared__ float hin[HH], hout[HH], ein[DD], eout[DD];
    int t = threadIdx.x;
    if (t < HH) {
        hin[t]  = fmaxf(Ew1[t] + Eb1[t], 0.f);
        hout[t] = fmaxf(Eb1[t], 0.f);
    }
    __syncthreads();
    if (t < DD) {
        float si = Eb2[t], so = Eb2[t];
        for (int j = 0; j < HH; j++) {
            si += hin[j]  * Ew2[j * DD + t];
            so += hout[j] * Ew2[j * DD + t];
        }
        ein[t]  = fmaxf(si, 0.f);
        eout[t] = fmaxf(so, 0.f);
    }
    __syncthreads();
    if (t < HH) {
        float bp = Pb1[t], bc = Cb1[t];
        for (int d = 0; d < DD; d++) {
            bp += eout[d] * Pw1[(2 * DD + d) * HH + t];
            bc += ein[d]  * Cw1[(2 * DD + d) * HH + t];
        }
        biasP[t] = bp;
        biasC[t] = bc;
    }
}
__global__ void count_kernel(const int* __restrict__ si, const int* __restrict__ pi,
                             int* __restrict__ cs, int* __restrict__ cp, int E) {
    int e = blockIdx.x * blockDim.x + threadIdx.x;
    if (e < E) {
        atomicAdd(&cs[si[e]], 1);
        atomicAdd(&cp[pi[e]], 1);
    }
}
// W [K][N] fp32 -> tf32 fragment order
__global__ void convert_w(const float* __restrict__ W, uint32_t* __restrict__ out, int K, int N) {
    int i = blockIdx.x * blockDim.x + threadIdx.x;
    if (i >= K * N) return;
    int k = i / N, n = i - k * N;
    int NT = N >> 3;
    int wi = ((k >> 3) * NT + (n >> 3)) * 64 + ((n & 7) * 4 + (k & 3)) * 2 + ((k >> 2) & 1);
    out[wi] = tf32r(W[i]);
}

// ---------------- kernel: hidden = MLP_V(batch_token) ----------------
__global__ __launch_bounds__(256, 1) void mlp_v_tf(
    const float* __restrict__ x,
    const float* __restrict__ Vb1, const float* __restrict__ Vb2,
    float* __restrict__ hidden, int Nn) {
    extern __shared__ char sm[];
    uint32_t sbase = smem_u32(sm);
    const int tid = threadIdx.x, wid = tid >> 5, lane = tid & 31;
    if (tid < 256) ((float*)(sm + OFF_BIAS1))[tid] = Vb1[tid];
    if (tid < 128) ((float*)(sm + OFF_BIAS2))[tid] = Vb2[tid];
    const int i0 = blockIdx.x * 64;
#pragma unroll
    for (int it = 0; it < 8; it++) {            // 64 rows * 32 float4
        int lin = tid + it * 256;
        int r = lin >> 5, q = lin & 31, k0 = q * 4;
        int node = i0 + r;
        float4 v = make_float4(0.f, 0.f, 0.f, 0.f);
        if (node < Nn) v = *(const float4*)(x + (size_t)node * 128 + k0);
        stA4(sm, OFF_A, k0 >> 3, r, k0, v);
    }
    float d[2][8][4];
#pragma unroll
    for (int a = 0; a < 2; a++)
#pragma unroll
        for (int b = 0; b < 8; b++)
#pragma unroll
            for (int c = 0; c < 4; c++) d[a][b][c] = 0.f;
    gemm_tf32<16, 32, 8>(sm, sbase, OFF_A, 0, g_V1f, d);
    epilogue1_T(sm, d, (const float*)(sm + OFF_BIAS1));
    float d2[2][4][4];
#pragma unroll
    for (int a = 0; a < 2; a++)
#pragma unroll
        for (int b = 0; b < 4; b++)
#pragma unroll
            for (int c = 0; c < 4; c++) d2[a][b][c] = 0.f;
    gemm_tf32<32, 16, 4>(sm, sbase, OFF_T, 0, g_V2f, d2);
    const float* b2 = (const float*)(sm + OFF_BIAS2);
    const int warpM = wid >> 2, warpG = wid & 3, g8 = lane >> 2, tig = lane & 3;
#pragma unroll
    for (int mt = 0; mt < 2; mt++) {
        int r0 = warpM * 32 + mt * 16 + g8;
        int n0 = i0 + r0, n1 = i0 + r0 + 8;
#pragma unroll
        for (int j = 0; j < 4; j++) {
            int c = warpG * 32 + j * 8 + tig * 2;
            if (n0 < Nn) {
                float2 o = make_float2(fmaxf(d2[mt][j][0] + b2[c], 0.f),
                                       fmaxf(d2[mt][j][1] + b2[c + 1], 0.f));
                *(float2*)(hidden + (size_t)n0 * 128 + c) = o;
            }
            if (n1 < Nn) {
                float2 o = make_float2(fmaxf(d2[mt][j][2] + b2[c], 0.f),
                                       fmaxf(d2[mt][j][3] + b2[c + 1], 0.f));
                *(float2*)(hidden + (size_t)n1 * 128 + c) = o;
            }
        }
    }
}

// ---------------- kernel: edge MLPs + scatter ----------------
__device__ void edge_mlp_pass(char* sm, uint32_t sbase, int kXor,
                              const uint32_t* w1f, const uint32_t* w2f,
                              const float* b1, const float* b2,
                              const int* scatIdx, float* dst) {
    const int tid = threadIdx.x, wid = tid >> 5, lane = tid & 31;
    float d[2][8][4];
#pragma unroll
    for (int a = 0; a < 2; a++)
#pragma unroll
        for (int b = 0; b < 8; b++)
#pragma unroll
            for (int c = 0; c < 4; c++) d[a][b][c] = 0.f;
    gemm_tf32<32, 32, 8>(sm, sbase, OFF_A, kXor, w1f, d);
    epilogue1_T(sm, d, b1);
    float d2[2][4][4];
#pragma unroll
    for (int a = 0; a < 2; a++)
#pragma unroll
        for (int b = 0; b < 4; b++)
#pragma unroll
            for (int c = 0; c < 4; c++) d2[a][b][c] = 0.f;
    gemm_tf32<32, 16, 4>(sm, sbase, OFF_T, 0, w2f, d2);
    const int warpM = wid >> 2, warpG = wid & 3, g8 = lane >> 2, tig = lane & 3;
#pragma unroll
    for (int mt = 0; mt < 2; mt++) {
        int r0 = warpM * 32 + mt * 16 + g8;
        int ia = scatIdx[r0], ib = scatIdx[r0 + 8];
#pragma unroll
        for (int j = 0; j < 4; j++) {
            int c = warpG * 32 + j * 8 + tig * 2;
            if (ia >= 0)
                red_add_v2(dst + (size_t)ia * 128 + c,
                           fmaxf(d2[mt][j][0] + b2[c], 0.f),
                           fmaxf(d2[mt][j][1] + b2[c + 1], 0.f));
            if (ib >= 0)
                red_add_v2(dst + (size_t)ib * 128 + c,
                           fmaxf(d2[mt][j][2] + b2[c], 0.f),
                           fmaxf(d2[mt][j][3] + b2[c + 1], 0.f));
        }
    }
    __syncthreads();
}

__global__ __launch_bounds__(256, 1) void edge_tf(
    const float* __restrict__ hidden,
    const int* __restrict__ self_idx, const int* __restrict__ parent_idx,
    const float* __restrict__ biasP, const float* __restrict__ Pb2,
    const float* __restrict__ biasC, const float* __restrict__ Cb2,
    float* __restrict__ sp, float* __restrict__ sc, int E) {
    extern __shared__ char sm[];
    uint32_t sbase = smem_u32(sm);
    const int tid = threadIdx.x;
    int* sIdx = (int*)(sm + OFF_AUX);
    int* pIdx = sIdx + 64;
    float* bC1 = (float*)(sm + OFF_AUX + 512);   // 256 f
    float* bC2 = (float*)(sm + OFF_AUX + 1536);  // 128 f
    const int e0 = blockIdx.x * 64;
    if (tid < 64) {
        int e = e0 + tid;
        sIdx[tid] = (e < E) ? self_idx[e] : -1;
        pIdx[tid] = (e < E) ? parent_idx[e] : -1;
    }
    if (tid < 256) {
        ((float*)(sm + OFF_BIAS1))[tid] = biasP[tid];
        bC1[tid] = biasC[tid];
    }
    if (tid < 128) {
        ((float*)(sm + OFF_BIAS2))[tid] = Pb2[tid];
        bC2[tid] = Cb2[tid];
    }
    __syncthreads();
    // stage A = [parent | self] fragments (K=256), once for both MLPs
#pragma unroll
    for (int it = 0; it < 16; it++) {
        int lin = tid + it * 256;
        int r = lin >> 6, q = lin & 63, k0 = q * 4;
        int idx = (k0 < 128) ? pIdx[r] : sIdx[r];
        float4 v = make_float4(0.f, 0.f, 0.f, 0.f);
        if (idx >= 0) v = *(const float4*)(hidden + (size_t)idx * 128 + (k0 & 127));
        stA4(sm, OFF_A, k0 >> 3, r, k0, v);
    }
    // MLP_P: [parent|self] natural order, scatter by self
    edge_mlp_pass(sm, sbase, 0, g_P1f, g_P2f,
                  (const float*)(sm + OFF_BIAS1), (const float*)(sm + OFF_BIAS2), sIdx, sp);
    // MLP_C: [self|parent] = A tiles XOR 16, scatter by parent
    edge_mlp_pass(sm, sbase, 16, g_C1f, g_C2f, bC1, bC2, pIdx, sc);
}

// ---------------- kernel: node aggregation ----------------
__global__ __launch_bounds__(256, 1) void node_tf(
    const float* __restrict__ hidden,
    const float* __restrict__ sp, const float* __restrict__ sc,
    const int* __restrict__ cntS, const int* __restrict__ cntP,
    const float* __restrict__ root_mask, const float* __restrict__ leaf_mask,
    const float* __restrict__ start_tok, const float* __restrict__ end_tok,
    const float* __restrict__ Ab1, const float* __restrict__ Ab2,
    float* __restrict__ out, int Nn) {
    extern __shared__ char sm[];
    uint32_t sbase = smem_u32(sm);
    const int tid = threadIdx.x, wid = tid >> 5, lane = tid & 31;
    float4* rowsc = (float4*)(sm + OFF_AUX);      // 64 * 16 B
    float* stok = (float*)(sm + OFF_AUX + 1024);  // 512 B
    float* etok = (float*)(sm + OFF_AUX + 1536);  // 512 B
    const int i0 = blockIdx.x * 64;
    if (tid < 64) {
        int node = i0 + tid;
        float4 rs = make_float4(1.f, 1.f, 0.f, 0.f);
        if (node < Nn) {
            int csv = cntS[node]; if (csv < 1) csv = 1;
            int cpv = cntP[node]; if (cpv < 1) cpv = 1;
            rs = make_float4(1.0f / (float)csv, 1.0f / (float)cpv,
                             root_mask[node], leaf_mask[node]);
        }
        rowsc[tid] = rs;
    }
    if (tid < 128) {
        stok[tid] = start_tok[tid];
        etok[tid] = end_tok[tid];
    }
    if (tid < 256) ((float*)(sm + OFF_BIAS1))[tid] = Ab1[tid];
    if (tid < 128) ((float*)(sm + OFF_BIAS2))[tid] = Ab2[tid];
    __syncthreads();
    // stage A = [hidden | Sp | Sc], K=384
#pragma unroll
    for (int it = 0; it < 24; it++) {
        int lin = tid + it * 256;        // 64 * 96
        int r = lin / 96, q = lin - r * 96, k0 = q * 4;
        int node = i0 + r;
        float4 v = make_float4(0.f, 0.f, 0.f, 0.f);
        if (node < Nn) {
            int c = k0 & 127;
            if (k0 < 128) {
                v = *(const float4*)(hidden + (size_t)node * 128 + c);
            } else if (k0 < 256) {
                float4 s = *(const float4*)(sp + (size_t)node * 128 + c);
                float4 rs = rowsc[r];
                v.x = s.x * rs.x + rs.z * stok[c + 0];
                v.y = s.y * rs.x + rs.z * stok[c + 1];
                v.z = s.z * rs.x + rs.z * stok[c + 2];
                v.w = s.w * rs.x + rs.z * stok[c + 3];
            } else {
                float4 s = *(const float4*)(sc + (size_t)node * 128 + c);
                float4 rs = rowsc[r];
                v.x = s.x * rs.y + rs.w * etok[c + 0];
                v.y = s.y * rs.y + rs.w * etok[c + 1];
                v.z = s.z * rs.y + rs.w * etok[c + 2];
                v.w = s.w * rs.y + rs.w * etok[c + 3];
            }
        }
        stA4(sm, OFF_A, k0 >> 3, r, k0, v);
    }
    float d[2][8][4];
#pragma unroll
    for (int a = 0; a < 2; a++)
#pragma unroll
        for (int b = 0; b < 8; b++)
#pragma unroll
            for (int c = 0; c < 4; c++) d[a][b][c] = 0.f;
    gemm_tf32<48, 32, 8>(sm, sbase, OFF_A, 0, g_A1f, d);
    epilogue1_T(sm, d, (const float*)(sm + OFF_BIAS1));
    float d2[2][4][4];
#pragma unroll
    for (int a = 0; a < 2; a++)
#pragma unroll
        for (int b = 0; b < 4; b++)
#pragma unroll
            for (int c = 0; c < 4; c++) d2[a][b][c] = 0.f;
    gemm_tf32<32, 16, 4>(sm, sbase, OFF_T, 0, g_A2f, d2);
    const float* b2 = (const float*)(sm + OFF_BIAS2);
    const int warpM = wid >> 2, warpG = wid & 3, g8 = lane >> 2, tig = lane & 3;
#pragma unroll
    for (int mt = 0; mt < 2; mt++) {
        int r0 = warpM * 32 + mt * 16 + g8;
        int n0 = i0 + r0, n1 = i0 + r0 + 8;
#pragma unroll
        for (int j = 0; j < 4; j++) {
            int c = warpG * 32 + j * 8 + tig * 2;
            if (n0 < Nn) {
                float2 h = *(const float2*)(hidden + (size_t)n0 * 128 + c);
                float2 o = make_float2(h.x + fmaxf(d2[mt][j][0] + b2[c], 0.f),
                                       h.y + fmaxf(d2[mt][j][1] + b2[c + 1], 0.f));
                *(float2*)(out + (size_t)n0 * 128 + c) = o;
            }
            if (n1 < Nn) {
                float2 h = *(const float2*)(hidden + (size_t)n1 * 128 + c);
                float2 o = make_float2(h.x + fmaxf(d2[mt][j][2] + b2[c], 0.f),
                                       h.y + fmaxf(d2[mt][j][3] + b2[c + 1], 0.f));
                *(float2*)(out + (size_t)n1 * 128 + c) = o;
            }
        }
    }
}

// ---------------- host launch ----------------
extern "C" void kernel_launch(void* const* d_in, const int* in_sizes, int n_in,
                              void* d_out, int out_size) {
    const float* batch_token = (const float*)d_in[0];
    const int*   self_idx    = (const int*)d_in[1];
    const int*   parent_idx  = (const int*)d_in[2];
    const float* root_mask   = (const float*)d_in[3];
    const float* leaf_mask   = (const float*)d_in[4];
    const float* start_tok   = (const float*)d_in[5];
    const float* end_tok     = (const float*)d_in[6];
    const float* Vw1 = (const float*)d_in[7];
    const float* Vb1 = (const float*)d_in[8];
    const float* Vw2 = (const float*)d_in[9];
    const float* Vb2 = (const float*)d_in[10];
    const float* Ew1 = (const float*)d_in[11];
    const float* Eb1 = (const float*)d_in[12];
    const float* Ew2 = (const float*)d_in[13];
    const float* Eb2 = (const float*)d_in[14];
    const float* Pw1 = (const float*)d_in[15];
    const float* Pb1 = (const float*)d_in[16];
    const float* Pw2 = (const float*)d_in[17];
    const float* Pb2 = (const float*)d_in[18];
    const float* Cw1 = (const float*)d_in[19];
    const float* Cb1 = (const float*)d_in[20];
    const float* Cw2 = (const float*)d_in[21];
    const float* Cb2 = (const float*)d_in[22];
    const float* Aw1 = (const float*)d_in[23];
    const float* Ab1 = (const float*)d_in[24];
    const float* Aw2 = (const float*)d_in[25];
    const float* Ab2 = (const float*)d_in[26];

    const int Nn = in_sizes[0] / 128;
    const int E  = in_sizes[1];

    float *hid, *sp, *sc, *bP, *bC;
    int *cs, *cp;
    cudaGetSymbolAddress((void**)&hid, g_hidden);
    cudaGetSymbolAddress((void**)&sp,  g_sp);
    cudaGetSymbolAddress((void**)&sc,  g_sc);
    cudaGetSymbolAddress((void**)&cs,  g_cnt_self);
    cudaGetSymbolAddress((void**)&cp,  g_cnt_par);
    cudaGetSymbolAddress((void**)&bP,  g_biasP);
    cudaGetSymbolAddress((void**)&bC,  g_biasC);
    uint32_t *v1, *v2, *p1, *p2, *c1, *c2, *a1, *a2;
    cudaGetSymbolAddress((void**)&v1, g_V1f);
    cudaGetSymbolAddress((void**)&v2, g_V2f);
    cudaGetSymbolAddress((void**)&p1, g_P1f);
    cudaGetSymbolAddress((void**)&p2, g_P2f);
    cudaGetSymbolAddress((void**)&c1, g_C1f);
    cudaGetSymbolAddress((void**)&c2, g_C2f);
    cudaGetSymbolAddress((void**)&a1, g_A1f);
    cudaGetSymbolAddress((void**)&a2, g_A2f);

    cudaFuncSetAttribute(mlp_v_tf, cudaFuncAttributeMaxDynamicSharedMemorySize, SMEM_MLPV);
    cudaFuncSetAttribute(edge_tf,  cudaFuncAttributeMaxDynamicSharedMemorySize, SMEM_EDGE);
    cudaFuncSetAttribute(node_tf,  cudaFuncAttributeMaxDynamicSharedMemorySize, SMEM_NODE);

    convert_w<<<(128 * 256 + 255) / 256, 256>>>(Vw1, v1, 128, 256);
    convert_w<<<(256 * 128 + 255) / 256, 256>>>(Vw2, v2, 256, 128);
    convert_w<<<(256 * 256 + 255) / 256, 256>>>(Pw1, p1, 256, 256);
    convert_w<<<(256 * 128 + 255) / 256, 256>>>(Pw2, p2, 256, 128);
    convert_w<<<(256 * 256 + 255) / 256, 256>>>(Cw1, c1, 256, 256);
    convert_w<<<(256 * 128 + 255) / 256, 256>>>(Cw2, c2, 256, 128);
    convert_w<<<(384 * 256 + 255) / 256, 256>>>(Aw1, a1, 384, 256);
    convert_w<<<(256 * 128 + 255) / 256, 256>>>(Aw2, a2, 256, 128);

    precompute_kernel<<<1, 256>>>(Ew1, Eb1, Ew2, Eb2, Pw1, Pb1, Cw1, Cb1, bP, bC);
    cudaMemsetAsync(cs, 0, (size_t)Nn * sizeof(int));
    cudaMemsetAsync(cp, 0, (size_t)Nn * sizeof(int));
    count_kernel<<<(E + 255) / 256, 256>>>(self_idx, parent_idx, cs, cp, E);

    const int gN = (Nn + 63) / 64;
    const int gE = (E + 63) / 64;
    mlp_v_tf<<<gN, 256, SMEM_MLPV>>>(batch_token, Vb1, Vb2, hid, Nn);

    for (int hop = 0; hop < 3; hop++) {
        cudaMemsetAsync(sp, 0, (size_t)Nn * 128 * sizeof(float));
        cudaMemsetAsync(sc, 0, (size_t)Nn * 128 * sizeof(float));
        edge_tf<<<gE, 256, SMEM_EDGE>>>(hid, self_idx, parent_idx,
                                        bP, Pb2, bC, Cb2, sp, sc, E);
        float* o = (hop == 2) ? (float*)d_out : hid;
        node_tf<<<gN, 256, SMEM_NODE>>>(hid, sp, sc, cs, cp,
                                        root_mask, leaf_mask, start_tok, end_tok,
                                        Ab1, Ab2, o, Nn);
    }
}

// round 9
// speedup vs baseline: 2.5554x; 1.1820x over previous
#include <cuda_runtime.h>
#include <cstdint>

#define MAXN 250000
#define DD 128
#define HH 256

// ---------------- smem layout (byte offsets) ----------------
#define OFF_BIAS1 0        // 256 floats
#define OFF_BIAS2 1024     // 128 floats
#define OFF_AUX   1536     // kernel-specific (<= 4096 B)
#define OFF_BBUF  5632     // B ring buffer: 3 stages x up to 8 KB
#define OFF_T     30208    // layer-2 A fragments (64 KB)
#define OFF_A     95744    // layer-1 A fragments (up to 96 KB)

#define SMEM_MLPV (OFF_A + 16 * 2048)   // K=128 -> 128512
#define SMEM_EDGE (OFF_A + 32 * 2048)   // K=256 -> 161280
#define SMEM_NODE (OFF_A + 48 * 2048)   // K=384 -> 194048

// ---------------- device scratch ----------------
__device__ float g_hidden[MAXN * DD];
__device__ float g_sp[MAXN * DD];
__device__ float g_sc[MAXN * DD];
__device__ int   g_cnt_self[MAXN];
__device__ int   g_cnt_par[MAXN];
__device__ float g_biasP[HH];
__device__ float g_biasC[HH];

// weights in tf32 MMA-fragment order (pair-interleaved B tiles):
// word = (k>>3)*(NT*64) + (n>>4)*128 + ((n&7)*4+(k&3))*4 + ((n>>3)&1)*2 + ((k>>2)&1)
__device__ __align__(16) uint32_t g_V1f[128 * 256];
__device__ __align__(16) uint32_t g_V2f[256 * 128];
__device__ __align__(16) uint32_t g_P1f[256 * 256];
__device__ __align__(16) uint32_t g_P2f[256 * 128];
__device__ __align__(16) uint32_t g_C1f[256 * 256];
__device__ __align__(16) uint32_t g_C2f[256 * 128];
__device__ __align__(16) uint32_t g_A1f[384 * 256];
__device__ __align__(16) uint32_t g_A2f[256 * 128];

// ---------------- helpers ----------------
__device__ __forceinline__ uint32_t tf32r(float x) {
    uint32_t y;
    asm("cvt.rna.tf32.f32 %0, %1;" : "=r"(y) : "f"(x));
    return y;
}
__device__ __forceinline__ uint32_t smem_u32(const void* p) {
    uint32_t a;
    asm("{ .reg .u64 t; cvta.to.shared.u64 t, %1; cvt.u32.u64 %0, t; }" : "=r"(a) : "l"(p));
    return a;
}
__device__ __forceinline__ void cpasync16(uint32_t dst, const void* src) {
    asm volatile("cp.async.ca.shared.global [%0], [%1], 16;" :: "r"(dst), "l"(src));
}
#define CP_COMMIT() asm volatile("cp.async.commit_group;")
#define CP_WAIT(n)  asm volatile("cp.async.wait_group %0;" :: "n"(n))

__device__ __forceinline__ void mma_tf32(float* d, const uint32_t* a, uint32_t b0, uint32_t b1) {
    asm volatile(
        "mma.sync.aligned.m16n8k8.row.col.f32.tf32.tf32.f32 "
        "{%0,%1,%2,%3}, {%4,%5,%6,%7}, {%8,%9}, {%0,%1,%2,%3};"
        : "+f"(d[0]), "+f"(d[1]), "+f"(d[2]), "+f"(d[3])
        : "r"(a[0]), "r"(a[1]), "r"(a[2]), "r"(a[3]), "r"(b0), "r"(b1));
}
__device__ __forceinline__ void red_add_v2(float* p, float x, float y) {
    asm volatile("red.global.add.v2.f32 [%0], {%1,%2};" :: "l"(p), "f"(x), "f"(y) : "memory");
}

// store float4 (row r, cols k0..k0+3, k0%4==0) into A-fragment layout at offA
__device__ __forceinline__ void stA4(char* sm, uint32_t offA, int kstep, int r, int k0, float4 v) {
    int tile = kstep * 4 + (r >> 4);
    int reg = ((k0 & 4) ? 2 : 0) + ((r & 8) ? 1 : 0);
    int la = (r & 7) * 4;
    uint32_t base = offA + (uint32_t)(tile * 128 + reg) * 4u + (uint32_t)la * 16u;
    *(uint32_t*)(sm + base)      = tf32r(v.x);
    *(uint32_t*)(sm + base + 16) = tf32r(v.y);
    *(uint32_t*)(sm + base + 32) = tf32r(v.z);
    *(uint32_t*)(sm + base + 48) = tf32r(v.w);
}

// ---------------- generic tf32 GEMM: 64 rows x (NT*8) cols, K = KS*8 ----------------
// 8 warps as 2(m) x 4(n); accum d[2][NTW][4]; B streamed via 3-stage cp.async ring.
// NOTE: caller must __syncthreads() after staging A before calling.
template <int KS, int NT, int NTW>
__device__ void gemm_tf32(char* sm, uint32_t sbase, uint32_t offA, int kXor,
                          const uint32_t* gB, float (&d)[2][NTW][4]) {
    const int tid = threadIdx.x, wid = tid >> 5, lane = tid & 31;
    const int warpM = wid >> 2, warpG = wid & 3;
    const int chunkB = NT * 256;                 // bytes per k8 chunk
    const int cpN = chunkB / (16 * 256);         // cp.async per thread (2 or 1)
#pragma unroll
    for (int p = 0; p < 2; p++) {
        if (p < KS) {
            uint32_t dst = sbase + OFF_BBUF + (uint32_t)p * chunkB;
            const char* src = (const char*)gB + (size_t)p * chunkB;
#pragma unroll
            for (int i = 0; i < cpN; i++) {
                int f = tid + i * 256;
                cpasync16(dst + f * 16, src + f * 16);
            }
            CP_COMMIT();
        }
    }
    for (int t = 0; t < KS; t++) {
        int kst = t ^ kXor;
        uint32_t a[2][4];
#pragma unroll
        for (int mt = 0; mt < 2; mt++) {
            uint32_t addr = offA + (uint32_t)((kst * 4 + warpM * 2 + mt) * 128 + lane * 4) * 4u;
            uint4 va = *(const uint4*)(sm + addr);
            a[mt][0] = va.x; a[mt][1] = va.y; a[mt][2] = va.z; a[mt][3] = va.w;
        }
        if (t + 1 < KS) { CP_WAIT(1); } else { CP_WAIT(0); }
        __syncthreads();
        if (t + 2 < KS) {
            uint32_t dst = sbase + OFF_BBUF + (uint32_t)((t + 2) % 3) * chunkB;
            const char* src = (const char*)gB + (size_t)(t + 2) * chunkB;
#pragma unroll
            for (int i = 0; i < cpN; i++) {
                int f = tid + i * 256;
                cpasync16(dst + f * 16, src + f * 16);
            }
            CP_COMMIT();
        }
        uint32_t bbase = sbase + OFF_BBUF + (uint32_t)(t % 3) * chunkB;
        // B pair-interleaved: one LDS.128 serves two adjacent n-tiles
#pragma unroll
        for (int jp = 0; jp < NTW / 2; jp++) {
            uint32_t baddr = bbase + (uint32_t)((warpG * (NTW / 2) + jp) * 128 + lane * 4) * 4u;
            uint4 vb;
            asm volatile("ld.shared.v4.u32 {%0,%1,%2,%3}, [%4];"
                         : "=r"(vb.x), "=r"(vb.y), "=r"(vb.z), "=r"(vb.w) : "r"(baddr));
            mma_tf32(d[0][2 * jp],     a[0], vb.x, vb.y);
            mma_tf32(d[1][2 * jp],     a[1], vb.x, vb.y);
            mma_tf32(d[0][2 * jp + 1], a[0], vb.z, vb.w);
            mma_tf32(d[1][2 * jp + 1], a[1], vb.z, vb.w);
        }
    }
}

// layer-1 epilogue: relu(+bias1) -> layer-2 A fragments at OFF_T (STS.64 pairs)
__device__ void epilogue1_T(char* sm, float (&d)[2][8][4], const float* b1) {
    const int tid = threadIdx.x, wid = tid >> 5, lane = tid & 31;
    const int warpM = wid >> 2, warpG = wid & 3;
    const int g8 = lane >> 2, tig = lane & 3;
    __syncthreads();  // all layer-1 B-ring reads done before T overwrites matter? (T disjoint; this also orders prior gemm)
#pragma unroll
    for (int mt = 0; mt < 2; mt++) {
        int rt = warpM * 2 + mt;
#pragma unroll
        for (int j = 0; j < 8; j++) {
            int c = warpG * 64 + j * 8 + tig * 2;
            float v00 = fmaxf(d[mt][j][0] + b1[c],     0.f);
            float v01 = fmaxf(d[mt][j][1] + b1[c + 1], 0.f);
            float v10 = fmaxf(d[mt][j][2] + b1[c],     0.f);
            float v11 = fmaxf(d[mt][j][3] + b1[c + 1], 0.f);
            int tile = (c >> 3) * 4 + rt;
            int word = tile * 128 + (g8 * 4 + (c & 3)) * 4 + ((c & 4) ? 2 : 0);
            uint32_t addr = (uint32_t)OFF_T + (uint32_t)word * 4u;
            *(uint2*)(sm + addr)      = make_uint2(tf32r(v00), tf32r(v10));
            *(uint2*)(sm + addr + 16) = make_uint2(tf32r(v01), tf32r(v11));
        }
    }
    __syncthreads();
}

// ---------------- prep kernels ----------------
// one kernel: all 8 weight conversions + degree counts (cs/cp pre-zeroed by memset)
__global__ void prep_w(
    const float* __restrict__ V1, const float* __restrict__ V2,
    const float* __restrict__ P1, const float* __restrict__ P2,
    const float* __restrict__ C1, const float* __restrict__ C2,
    const float* __restrict__ A1, const float* __restrict__ A2,
    uint32_t* __restrict__ o1, uint32_t* __restrict__ o2,
    uint32_t* __restrict__ o3, uint32_t* __restrict__ o4,
    uint32_t* __restrict__ o5, uint32_t* __restrict__ o6,
    uint32_t* __restrict__ o7, uint32_t* __restrict__ o8,
    const int* __restrict__ si, const int* __restrict__ pi,
    int* __restrict__ cs, int* __restrict__ cp, int E) {
    int gid = blockIdx.x * blockDim.x + threadIdx.x;
    const int T0 = 32768, T1 = 65536, T2 = 131072, T3 = 163840;
    const int T4 = 229376, T5 = 262144, T6 = 360448, T7 = 393216;
    if (gid < T7) {
        const float* W; uint32_t* O; int K, N, i;
        if (gid < T0)      { W = V1; O = o1; K = 128; N = 256; i = gid; }
        else if (gid < T1) { W = V2; O = o2; K = 256; N = 128; i = gid - T0; }
        else if (gid < T2) { W = P1; O = o3; K = 256; N = 256; i = gid - T1; }
        else if (gid < T3) { W = P2; O = o4; K = 256; N = 128; i = gid - T2; }
        else if (gid < T4) { W = C1; O = o5; K = 256; N = 256; i = gid - T3; }
        else if (gid < T5) { W = C2; O = o6; K = 256; N = 128; i = gid - T4; }
        else if (gid < T6) { W = A1; O = o7; K = 384; N = 256; i = gid - T5; }
        else               { W = A2; O = o8; K = 256; N = 128; i = gid - T6; }
        int k = i / N, n = i - k * N;
        int NT = N >> 3;
        int wi = (k >> 3) * (NT * 64) + (n >> 4) * 128 + ((n & 7) * 4 + (k & 3)) * 4
               + (((n >> 3) & 1) ? 2 : 0) + ((k >> 2) & 1);
        O[wi] = tf32r(W[i]);
        (void)K;
    } else {
        int e = gid - T7;
        if (e < E) {
            atomicAdd(&cs[si[e]], 1);
            atomicAdd(&cp[pi[e]], 1);
        }
    }
}

__global__ void prep_bias(const float* __restrict__ Ew1, const float* __restrict__ Eb1,
                          const float* __restrict__ Ew2, const float* __restrict__ Eb2,
                          const float* __restrict__ Pw1, const float* __restrict__ Pb1,
                          const float* __restrict__ Cw1, const float* __restrict__ Cb1,
                          float* __restrict__ biasP, float* __restrict__ biasC) {
    __shared__ float hin[HH], hout[HH], ein[DD], eout[DD];
    int t = threadIdx.x;
    if (t < HH) {
        hin[t]  = fmaxf(Ew1[t] + Eb1[t], 0.f);
        hout[t] = fmaxf(Eb1[t], 0.f);
    }
    __syncthreads();
    if (t < DD) {
        float si = Eb2[t], so = Eb2[t];
        for (int j = 0; j < HH; j++) {
            si += hin[j]  * Ew2[j * DD + t];
            so += hout[j] * Ew2[j * DD + t];
        }
        ein[t]  = fmaxf(si, 0.f);
        eout[t] = fmaxf(so, 0.f);
    }
    __syncthreads();
    if (t < HH) {
        float bp = Pb1[t], bc = Cb1[t];
        for (int d = 0; d < DD; d++) {
            bp += eout[d] * Pw1[(2 * DD + d) * HH + t];
            bc += ein[d]  * Cw1[(2 * DD + d) * HH + t];
        }
        biasP[t] = bp;
        biasC[t] = bc;
    }
}

// ---------------- kernel: hidden = MLP_V(batch_token) ----------------
__global__ __launch_bounds__(256, 1) void mlp_v_tf(
    const float* __restrict__ x,
    const float* __restrict__ Vb1, const float* __restrict__ Vb2,
    float* __restrict__ hidden, int Nn) {
    extern __shared__ char sm[];
    uint32_t sbase = smem_u32(sm);
    const int tid = threadIdx.x, wid = tid >> 5, lane = tid & 31;
    if (tid < 256) ((float*)(sm + OFF_BIAS1))[tid] = Vb1[tid];
    if (tid < 128) ((float*)(sm + OFF_BIAS2))[tid] = Vb2[tid];
    const int i0 = blockIdx.x * 64;
#pragma unroll
    for (int it = 0; it < 8; it++) {
        int lin = tid + it * 256;
        int r = lin >> 5, q = lin & 31, k0 = q * 4;
        int node = i0 + r;
        float4 v = make_float4(0.f, 0.f, 0.f, 0.f);
        if (node < Nn) v = *(const float4*)(x + (size_t)node * 128 + k0);
        stA4(sm, OFF_A, k0 >> 3, r, k0, v);
    }
    __syncthreads();
    float d[2][8][4];
#pragma unroll
    for (int a = 0; a < 2; a++)
#pragma unroll
        for (int b = 0; b < 8; b++)
#pragma unroll
            for (int c = 0; c < 4; c++) d[a][b][c] = 0.f;
    gemm_tf32<16, 32, 8>(sm, sbase, OFF_A, 0, g_V1f, d);
    epilogue1_T(sm, d, (const float*)(sm + OFF_BIAS1));
    float d2[2][4][4];
#pragma unroll
    for (int a = 0; a < 2; a++)
#pragma unroll
        for (int b = 0; b < 4; b++)
#pragma unroll
            for (int c = 0; c < 4; c++) d2[a][b][c] = 0.f;
    gemm_tf32<32, 16, 4>(sm, sbase, OFF_T, 0, g_V2f, d2);
    const float* b2 = (const float*)(sm + OFF_BIAS2);
    const int warpM = wid >> 2, warpG = wid & 3, g8 = lane >> 2, tig = lane & 3;
#pragma unroll
    for (int mt = 0; mt < 2; mt++) {
        int r0 = warpM * 32 + mt * 16 + g8;
        int n0 = i0 + r0, n1 = i0 + r0 + 8;
#pragma unroll
        for (int j = 0; j < 4; j++) {
            int c = warpG * 32 + j * 8 + tig * 2;
            if (n0 < Nn) {
                float2 o = make_float2(fmaxf(d2[mt][j][0] + b2[c], 0.f),
                                       fmaxf(d2[mt][j][1] + b2[c + 1], 0.f));
                *(float2*)(hidden + (size_t)n0 * 128 + c) = o;
            }
            if (n1 < Nn) {
                float2 o = make_float2(fmaxf(d2[mt][j][2] + b2[c], 0.f),
                                       fmaxf(d2[mt][j][3] + b2[c + 1], 0.f));
                *(float2*)(hidden + (size_t)n1 * 128 + c) = o;
            }
        }
    }
}

// ---------------- kernel: edge MLPs + scatter ----------------
__device__ void edge_mlp_pass(char* sm, uint32_t sbase, int kXor,
                              const uint32_t* w1f, const uint32_t* w2f,
                              const float* b1, const float* b2,
                              const int* scatIdx, float* dst) {
    const int tid = threadIdx.x, wid = tid >> 5, lane = tid & 31;
    float d[2][8][4];
#pragma unroll
    for (int a = 0; a < 2; a++)
#pragma unroll
        for (int b = 0; b < 8; b++)
#pragma unroll
            for (int c = 0; c < 4; c++) d[a][b][c] = 0.f;
    gemm_tf32<32, 32, 8>(sm, sbase, OFF_A, kXor, w1f, d);
    epilogue1_T(sm, d, b1);
    float d2[2][4][4];
#pragma unroll
    for (int a = 0; a < 2; a++)
#pragma unroll
        for (int b = 0; b < 4; b++)
#pragma unroll
            for (int c = 0; c < 4; c++) d2[a][b][c] = 0.f;
    gemm_tf32<32, 16, 4>(sm, sbase, OFF_T, 0, w2f, d2);
    const int warpM = wid >> 2, warpG = wid & 3, g8 = lane >> 2, tig = lane & 3;
#pragma unroll
    for (int mt = 0; mt < 2; mt++) {
        int r0 = warpM * 32 + mt * 16 + g8;
        int ia = scatIdx[r0], ib = scatIdx[r0 + 8];
#pragma unroll
        for (int j = 0; j < 4; j++) {
            int c = warpG * 32 + j * 8 + tig * 2;
            if (ia >= 0)
                red_add_v2(dst + (size_t)ia * 128 + c,
                           fmaxf(d2[mt][j][0] + b2[c], 0.f),
                           fmaxf(d2[mt][j][1] + b2[c + 1], 0.f));
            if (ib >= 0)
                red_add_v2(dst + (size_t)ib * 128 + c,
                           fmaxf(d2[mt][j][2] + b2[c], 0.f),
                           fmaxf(d2[mt][j][3] + b2[c + 1], 0.f));
        }
    }
    __syncthreads();
}

__global__ __launch_bounds__(256, 1) void edge_tf(
    const float* __restrict__ hidden,
    const int* __restrict__ self_idx, const int* __restrict__ parent_idx,
    const float* __restrict__ biasP, const float* __restrict__ Pb2,
    const float* __restrict__ biasC, const float* __restrict__ Cb2,
    float* __restrict__ sp, float* __restrict__ sc, int E) {
    extern __shared__ char sm[];
    uint32_t sbase = smem_u32(sm);
    const int tid = threadIdx.x;
    int* sIdx = (int*)(sm + OFF_AUX);
    int* pIdx = sIdx + 64;
    float* bC1 = (float*)(sm + OFF_AUX + 512);
    float* bC2 = (float*)(sm + OFF_AUX + 1536);
    const int e0 = blockIdx.x * 64;
    if (tid < 64) {
        int e = e0 + tid;
        sIdx[tid] = (e < E) ? self_idx[e] : -1;
        pIdx[tid] = (e < E) ? parent_idx[e] : -1;
    }
    if (tid < 256) {
        ((float*)(sm + OFF_BIAS1))[tid] = biasP[tid];
        bC1[tid] = biasC[tid];
    }
    if (tid < 128) {
        ((float*)(sm + OFF_BIAS2))[tid] = Pb2[tid];
        bC2[tid] = Cb2[tid];
    }
    __syncthreads();
    // stage A = [parent | self] fragments (K=256), once for both MLPs
#pragma unroll
    for (int it = 0; it < 16; it++) {
        int lin = tid + it * 256;
        int r = lin >> 6, q = lin & 63, k0 = q * 4;
        int idx = (k0 < 128) ? pIdx[r] : sIdx[r];
        float4 v = make_float4(0.f, 0.f, 0.f, 0.f);
        if (idx >= 0) v = *(const float4*)(hidden + (size_t)idx * 128 + (k0 & 127));
        stA4(sm, OFF_A, k0 >> 3, r, k0, v);
    }
    __syncthreads();
    // MLP_P: [parent|self] natural order, scatter by self
    edge_mlp_pass(sm, sbase, 0, g_P1f, g_P2f,
                  (const float*)(sm + OFF_BIAS1), (const float*)(sm + OFF_BIAS2), sIdx, sp);
    // MLP_C: [self|parent] = A k-tiles XOR 16, scatter by parent
    edge_mlp_pass(sm, sbase, 16, g_C1f, g_C2f, bC1, bC2, pIdx, sc);
}

// ---------------- kernel: node aggregation ----------------
__global__ __launch_bounds__(256, 1) void node_tf(
    const float* __restrict__ hidden,
    const float* __restrict__ sp, const float* __restrict__ sc,
    const int* __restrict__ cntS, const int* __restrict__ cntP,
    const float* __restrict__ root_mask, const float* __restrict__ leaf_mask,
    const float* __restrict__ start_tok, const float* __restrict__ end_tok,
    const float* __restrict__ Ab1, const float* __restrict__ Ab2,
    float* __restrict__ out, int Nn) {
    extern __shared__ char sm[];
    uint32_t sbase = smem_u32(sm);
    const int tid = threadIdx.x, wid = tid >> 5, lane = tid & 31;
    float4* rowsc = (float4*)(sm + OFF_AUX);
    float* stok = (float*)(sm + OFF_AUX + 1024);
    float* etok = (float*)(sm + OFF_AUX + 1536);
    const int i0 = blockIdx.x * 64;
    if (tid < 64) {
        int node = i0 + tid;
        float4 rs = make_float4(1.f, 1.f, 0.f, 0.f);
        if (node < Nn) {
            int csv = cntS[node]; if (csv < 1) csv = 1;
            int cpv = cntP[node]; if (cpv < 1) cpv = 1;
            rs = make_float4(1.0f / (float)csv, 1.0f / (float)cpv,
                             root_mask[node], leaf_mask[node]);
        }
        rowsc[tid] = rs;
    }
    if (tid < 128) {
        stok[tid] = start_tok[tid];
        etok[tid] = end_tok[tid];
    }
    if (tid < 256) ((float*)(sm + OFF_BIAS1))[tid] = Ab1[tid];
    if (tid < 128) ((float*)(sm + OFF_BIAS2))[tid] = Ab2[tid];
    __syncthreads();
#pragma unroll
    for (int it = 0; it < 24; it++) {
        int lin = tid + it * 256;
        int r = lin / 96, q = lin - r * 96, k0 = q * 4;
        int node = i0 + r;
        float4 v = make_float4(0.f, 0.f, 0.f, 0.f);
        if (node < Nn) {
            int c = k0 & 127;
            if (k0 < 128) {
                v = *(const float4*)(hidden + (size_t)node * 128 + c);
            } else if (k0 < 256) {
                float4 s = *(const float4*)(sp + (size_t)node * 128 + c);
                float4 rs = rowsc[r];
                v.x = s.x * rs.x + rs.z * stok[c + 0];
                v.y = s.y * rs.x + rs.z * stok[c + 1];
                v.z = s.z * rs.x + rs.z * stok[c + 2];
                v.w = s.w * rs.x + rs.z * stok[c + 3];
            } else {
                float4 s = *(const float4*)(sc + (size_t)node * 128 + c);
                float4 rs = rowsc[r];
                v.x = s.x * rs.y + rs.w * etok[c + 0];
                v.y = s.y * rs.y + rs.w * etok[c + 1];
                v.z = s.z * rs.y + rs.w * etok[c + 2];
                v.w = s.w * rs.y + rs.w * etok[c + 3];
            }
        }
        stA4(sm, OFF_A, k0 >> 3, r, k0, v);
    }
    __syncthreads();
    float d[2][8][4];
#pragma unroll
    for (int a = 0; a < 2; a++)
#pragma unroll
        for (int b = 0; b < 8; b++)
#pragma unroll
            for (int c = 0; c < 4; c++) d[a][b][c] = 0.f;
    gemm_tf32<48, 32, 8>(sm, sbase, OFF_A, 0, g_A1f, d);
    epilogue1_T(sm, d, (const float*)(sm + OFF_BIAS1));
    float d2[2][4][4];
#pragma unroll
    for (int a = 0; a < 2; a++)
#pragma unroll
        for (int b = 0; b < 4; b++)
#pragma unroll
            for (int c = 0; c < 4; c++) d2[a][b][c] = 0.f;
    gemm_tf32<32, 16, 4>(sm, sbase, OFF_T, 0, g_A2f, d2);
    const float* b2 = (const float*)(sm + OFF_BIAS2);
    const int warpM = wid >> 2, warpG = wid & 3, g8 = lane >> 2, tig = lane & 3;
#pragma unroll
    for (int mt = 0; mt < 2; mt++) {
        int r0 = warpM * 32 + mt * 16 + g8;
        int n0 = i0 + r0, n1 = i0 + r0 + 8;
#pragma unroll
        for (int j = 0; j < 4; j++) {
            int c = warpG * 32 + j * 8 + tig * 2;
            if (n0 < Nn) {
                float2 h = *(const float2*)(hidden + (size_t)n0 * 128 + c);
                float2 o = make_float2(h.x + fmaxf(d2[mt][j][0] + b2[c], 0.f),
                                       h.y + fmaxf(d2[mt][j][1] + b2[c + 1], 0.f));
                *(float2*)(out + (size_t)n0 * 128 + c) = o;
            }
            if (n1 < Nn) {
                float2 h = *(const float2*)(hidden + (size_t)n1 * 128 + c);
                float2 o = make_float2(h.x + fmaxf(d2[mt][j][2] + b2[c], 0.f),
                                       h.y + fmaxf(d2[mt][j][3] + b2[c + 1], 0.f));
                *(float2*)(out + (size_t)n1 * 128 + c) = o;
            }
        }
    }
}

// ---------------- host launch ----------------
extern "C" void kernel_launch(void* const* d_in, const int* in_sizes, int n_in,
                              void* d_out, int out_size) {
    const float* batch_token = (const float*)d_in[0];
    const int*   self_idx    = (const int*)d_in[1];
    const int*   parent_idx  = (const int*)d_in[2];
    const float* root_mask   = (const float*)d_in[3];
    const float* leaf_mask   = (const float*)d_in[4];
    const float* start_tok   = (const float*)d_in[5];
    const float* end_tok     = (const float*)d_in[6];
    const float* Vw1 = (const float*)d_in[7];
    const float* Vb1 = (const float*)d_in[8];
    const float* Vw2 = (const float*)d_in[9];
    const float* Vb2 = (const float*)d_in[10];
    const float* Ew1 = (const float*)d_in[11];
    const float* Eb1 = (const float*)d_in[12];
    const float* Ew2 = (const float*)d_in[13];
    const float* Eb2 = (const float*)d_in[14];
    const float* Pw1 = (const float*)d_in[15];
    const float* Pb1 = (const float*)d_in[16];
    const float* Pw2 = (const float*)d_in[17];
    const float* Pb2 = (const float*)d_in[18];
    const float* Cw1 = (const float*)d_in[19];
    const float* Cb1 = (const float*)d_in[20];
    const float* Cw2 = (const float*)d_in[21];
    const float* Cb2 = (const float*)d_in[22];
    const float* Aw1 = (const float*)d_in[23];
    const float* Ab1 = (const float*)d_in[24];
    const float* Aw2 = (const float*)d_in[25];
    const float* Ab2 = (const float*)d_in[26];

    const int Nn = in_sizes[0] / 128;
    const int E  = in_sizes[1];

    float *hid, *sp, *sc, *bP, *bC;
    int *cs, *cp;
    cudaGetSymbolAddress((void**)&hid, g_hidden);
    cudaGetSymbolAddress((void**)&sp,  g_sp);
    cudaGetSymbolAddress((void**)&sc,  g_sc);
    cudaGetSymbolAddress((void**)&cs,  g_cnt_self);
    cudaGetSymbolAddress((void**)&cp,  g_cnt_par);
    cudaGetSymbolAddress((void**)&bP,  g_biasP);
    cudaGetSymbolAddress((void**)&bC,  g_biasC);
    uint32_t *v1, *v2, *p1, *p2, *c1, *c2, *a1, *a2;
    cudaGetSymbolAddress((void**)&v1, g_V1f);
    cudaGetSymbolAddress((void**)&v2, g_V2f);
    cudaGetSymbolAddress((void**)&p1, g_P1f);
    cudaGetSymbolAddress((void**)&p2, g_P2f);
    cudaGetSymbolAddress((void**)&c1, g_C1f);
    cudaGetSymbolAddress((void**)&c2, g_C2f);
    cudaGetSymbolAddress((void**)&a1, g_A1f);
    cudaGetSymbolAddress((void**)&a2, g_A2f);

    cudaFuncSetAttribute(mlp_v_tf, cudaFuncAttributeMaxDynamicSharedMemorySize, SMEM_MLPV);
    cudaFuncSetAttribute(edge_tf,  cudaFuncAttributeMaxDynamicSharedMemorySize, SMEM_EDGE);
    cudaFuncSetAttribute(node_tf,  cudaFuncAttributeMaxDynamicSharedMemorySize, SMEM_NODE);

    // zero degree counts (memsets are not counted as kernel launches by the profiler skip)
    cudaMemsetAsync(cs, 0, (size_t)Nn * sizeof(int));
    cudaMemsetAsync(cp, 0, (size_t)Nn * sizeof(int));

    // launch #1: all weight conversions + degree counts
    {
        const int total = 393216 + E;
        prep_w<<<(total + 255) / 256, 256>>>(Vw1, Vw2, Pw1, Pw2, Cw1, Cw2, Aw1, Aw2,
                                             v1, v2, p1, p2, c1, c2, a1, a2,
                                             self_idx, parent_idx, cs, cp, E);
    }
    // launch #2: folded biases
    prep_bias<<<1, 256>>>(Ew1, Eb1, Ew2, Eb2, Pw1, Pb1, Cw1, Cb1, bP, bC);

    const int gN = (Nn + 63) / 64;
    const int gE = (E + 63) / 64;
    // launch #3
    mlp_v_tf<<<gN, 256, SMEM_MLPV>>>(batch_token, Vb1, Vb2, hid, Nn);

    for (int hop = 0; hop < 3; hop++) {
        cudaMemsetAsync(sp, 0, (size_t)Nn * 128 * sizeof(float));
        cudaMemsetAsync(sc, 0, (size_t)Nn * 128 * sizeof(float));
        // launches #4/#5 (hop0), #6 (hop1 edge <- ncu capture target), ...
        edge_tf<<<gE, 256, SMEM_EDGE>>>(hid, self_idx, parent_idx,
                                        bP, Pb2, bC, Cb2, sp, sc, E);
        float* o = (hop == 2) ? (float*)d_out : hid;
        node_tf<<<gN, 256, SMEM_NODE>>>(hid, sp, sc, cs, cp,
                                        root_mask, leaf_mask, start_tok, end_tok,
                                        Ab1, Ab2, o, Nn);
    }
}